// round 4
// baseline (speedup 1.0000x reference)
#include <cuda_runtime.h>

#define EMB 128
#define ETILE 32
#define OROWS 16
#define PROWS 8
#define MAXNODES 100000

typedef unsigned long long ull;

// Scratch (device globals: no allocations allowed in kernel_launch)
__device__ __align__(128) float g_Lp[MAXNODES * EMB];
__device__ __align__(128) float g_Rp[MAXNODES * EMB];
__device__ __align__(128) float g_conv[MAXNODES * EMB];
// paired-transposed weights: Wp[k2*EMB + j] = (W[j][2*k2], W[j][2*k2+1])
__device__ __align__(128) float2 g_WLP[64 * EMB];
__device__ __align__(128) float2 g_WRP[64 * EMB];
__device__ __align__(128) float2 g_WfP[64 * EMB];
__device__ __align__(128) float2 g_W1P[128 * EMB];
__device__ __align__(128) float2 g_W2P[64 * EMB];
__device__ int g_is64;

// ---- packed f32x2 helpers --------------------------------------------------
__device__ __forceinline__ ull pk2(float lo, float hi) {
    ull r;
    asm("mov.b64 %0, {%1, %2};" : "=l"(r) : "f"(lo), "f"(hi));
    return r;
}
__device__ __forceinline__ float upk_sum(ull a) {
    float lo, hi;
    asm("mov.b64 {%0, %1}, %2;" : "=f"(lo), "=f"(hi) : "l"(a));
    return lo + hi;
}
#define FMA2(acc, a, b) \
    asm("fma.rn.f32x2 %0, %1, %2, %3;" : "=l"(acc) : "l"(a), "l"(b), "l"(acc))

__device__ __forceinline__ void red_add_v4(float* p, float4 v) {
    asm volatile("red.global.add.v4.f32 [%0], {%1, %2, %3, %4};"
                 :: "l"(p), "f"(v.x), "f"(v.y), "f"(v.z), "f"(v.w) : "memory");
}

// ---------------------------------------------------------------------------
// Detect whether edge_indices buffer is int64 or int32 (JAX x64-off pitfall).
// ---------------------------------------------------------------------------
__global__ void detect_idx_kernel(const long long* __restrict__ e, int n64_safe) {
    if (blockIdx.x == 0 && threadIdx.x == 0) {
        int m = n64_safe < 64 ? n64_safe : 64;
        int ok = 1;
        for (int i = 0; i < m; i++) {
            long long v = e[i];
            if (v < 0 || v >= (1LL << 31)) { ok = 0; break; }
        }
        g_is64 = ok;
    }
}

// ---------------------------------------------------------------------------
// prep: zero g_conv + build paired-transposed weights (coalesced writes).
// ---------------------------------------------------------------------------
__global__ void prep_kernel(const float* __restrict__ Wl, const float* __restrict__ Wr,
                            const float* __restrict__ Wf, const float* __restrict__ W1,
                            const float* __restrict__ W2, int n4) {
    const int idx = blockIdx.x * blockDim.x + threadIdx.x;
    if (idx < n4) ((float4*)g_conv)[idx] = make_float4(0.f, 0.f, 0.f, 0.f);
    if (idx < 64 * EMB) {
        const int k2 = idx >> 7, j = idx & 127;
        g_WLP[idx] = make_float2(Wl[j * EMB + 2 * k2], Wl[j * EMB + 2 * k2 + 1]);
        g_WRP[idx] = make_float2(Wr[j * EMB + 2 * k2], Wr[j * EMB + 2 * k2 + 1]);
        g_WfP[idx] = make_float2(Wf[j * EMB + 2 * k2], Wf[j * EMB + 2 * k2 + 1]);
        g_W2P[idx] = make_float2(W2[j * EMB + 2 * k2], W2[j * EMB + 2 * k2 + 1]);
    }
    if (idx < 128 * EMB) {
        const int k2 = idx >> 7, j = idx & 127;
        g_W1P[idx] = make_float2(W1[j * 2 * EMB + 2 * k2], W1[j * 2 * EMB + 2 * k2 + 1]);
    }
}

// ---------------------------------------------------------------------------
// Merged projections: out[m,j] = sum_k A[m,k] * W[j,k] (+ b[j] for left side)
// Thread j owns column j; paired weights -> f32x2 FMA.
// ---------------------------------------------------------------------------
__global__ __launch_bounds__(128) void proj_kernel(
    const float* __restrict__ left, const float* __restrict__ right,
    const float* __restrict__ bL, int n_left, int n_right, int blocksL)
{
    __shared__ __align__(16) float As[PROWS][EMB];
    const int j = threadIdx.x;

    const float* __restrict__ A;
    const ull* __restrict__ WP;
    float* out; int n; float bj; int row0;
    if (blockIdx.x < blocksL) {
        A = left; WP = (const ull*)g_WLP; out = g_Lp; n = n_left;
        bj = bL[j]; row0 = blockIdx.x * 64;
    } else {
        A = right; WP = (const ull*)g_WRP; out = g_Rp; n = n_right;
        bj = 0.f; row0 = (blockIdx.x - blocksL) * 64;
    }

    for (int rt = 0; rt < 64; rt += PROWS) {
        const int rbase = row0 + rt;
        __syncthreads();
        for (int i = threadIdx.x; i < PROWS * 32; i += 128) {
            const int r = i >> 5, c4 = i & 31;
            float4 v = make_float4(0.f, 0.f, 0.f, 0.f);
            if (rbase + r < n)
                v = ((const float4*)(A + (size_t)(rbase + r) * EMB))[c4];
            ((float4*)As[r])[c4] = v;
        }
        __syncthreads();

        ull acc[PROWS];
#pragma unroll
        for (int r = 0; r < PROWS; r++) acc[r] = pk2(bj, 0.f);

#pragma unroll 2
        for (int k4 = 0; k4 < 32; k4++) {
            const ull wa = WP[(size_t)(2 * k4) * EMB + j];
            const ull wb = WP[(size_t)(2 * k4 + 1) * EMB + j];
#pragma unroll
            for (int r = 0; r < PROWS; r++) {
                const ulonglong2 x = ((const ulonglong2*)As[r])[k4];
                FMA2(acc[r], wa, x.x);
                FMA2(acc[r], wb, x.y);
            }
        }
#pragma unroll
        for (int r = 0; r < PROWS; r++)
            if (rbase + r < n) out[(size_t)(rbase + r) * EMB + j] = upk_sum(acc[r]);
    }
}

// ---------------------------------------------------------------------------
// Fused edge stage: joint = Lp[s] + Rp[d] + ef*w_edge; t = relu(joint*scale);
// msg = t @ Wf^T + b_final; red.v4 scatter into g_conv[d].
// 128 threads, ETILE=32 edges per block, f32x2 GEMM.
// ---------------------------------------------------------------------------
__global__ __launch_bounds__(128) void edge_kernel(
    const void* __restrict__ eidx_raw, const float* __restrict__ ef,
    const float* __restrict__ wedge, const float* __restrict__ bf,
    const float* __restrict__ scale_p, int n_edges)
{
    __shared__ __align__(16) float Ts[ETILE][EMB];
    __shared__ int Ss[ETILE];
    __shared__ int Dd[ETILE];
    __shared__ float Fs[ETILE];
    const int e0 = blockIdx.x * ETILE;
    const float scale = scale_p[0];
    const int tid = threadIdx.x;
    const int warp = tid >> 5, lane = tid & 31;
    const int is64 = g_is64;
    const long long* __restrict__ e64 = (const long long*)eidx_raw;
    const int* __restrict__ e32 = (const int*)eidx_raw;

    // Phase A: preload indices + edge features
    if (tid < ETILE) {
        const int ge = e0 + tid;
        int s = 0, d = -1; float f = 0.f;
        if (ge < n_edges) {
            if (is64) { s = (int)e64[ge]; d = (int)e64[n_edges + ge]; }
            else      { s = e32[ge];      d = e32[n_edges + ge]; }
            f = ef[ge];
        }
        Ss[tid] = s; Dd[tid] = d; Fs[tid] = f;
    }
    __syncthreads();

    // Phase B: gather + combine + relu into shared tile
    const float4 we = ((const float4*)wedge)[lane];
#pragma unroll
    for (int e = warp; e < ETILE; e += 4) {
        float4 t = make_float4(0.f, 0.f, 0.f, 0.f);
        const int d = Dd[e];
        if (d >= 0) {
            const int s = Ss[e];
            const float4 l = ((const float4*)(g_Lp + (size_t)s * EMB))[lane];
            const float4 r = ((const float4*)(g_Rp + (size_t)d * EMB))[lane];
            const float fe = Fs[e];
            t.x = fmaxf(fmaf(fe, we.x, l.x + r.x) * scale, 0.f);
            t.y = fmaxf(fmaf(fe, we.y, l.y + r.y) * scale, 0.f);
            t.z = fmaxf(fmaf(fe, we.z, l.z + r.z) * scale, 0.f);
            t.w = fmaxf(fmaf(fe, we.w, l.w + r.w) * scale, 0.f);
        }
        ((float4*)Ts[e])[lane] = t;
    }
    __syncthreads();

    // Phase C: GEMM — thread j computes msg[e][j] for all 32 edges (f32x2)
    ull acc[ETILE];
    const float bj = bf[tid];
#pragma unroll
    for (int e = 0; e < ETILE; e++) acc[e] = pk2(bj, 0.f);

    const ull* __restrict__ WP = (const ull*)g_WfP;
#pragma unroll 1
    for (int k4 = 0; k4 < 32; k4++) {
        const ull wa = WP[(size_t)(2 * k4) * EMB + tid];
        const ull wb = WP[(size_t)(2 * k4 + 1) * EMB + tid];
#pragma unroll
        for (int e = 0; e < ETILE; e++) {
            const ulonglong2 x = ((const ulonglong2*)Ts[e])[k4];  // broadcast LDS
            FMA2(acc[e], wa, x.x);
            FMA2(acc[e], wb, x.y);
        }
    }

    // Phase D: transpose through smem, then vectorized scatter (red.v4)
    __syncthreads();
#pragma unroll
    for (int e = 0; e < ETILE; e++) Ts[e][tid] = upk_sum(acc[e]);
    __syncthreads();

#pragma unroll
    for (int i = 0; i < ETILE / 4; i++) {
        const int e = warp * (ETILE / 4) + i;
        const int d = Dd[e];
        if (d >= 0) {
            const float4 m = ((const float4*)Ts[e])[lane];
            red_add_v4(&g_conv[(size_t)d * EMB + lane * 4], m);
        }
    }
}

// ---------------------------------------------------------------------------
// Output MLP: h = [conv*scale_post ; right];  u = relu(h@W1^T + b1);
// out = u@W2^T + b2.  128 threads, OROWS rows per block, f32x2 GEMMs.
// ---------------------------------------------------------------------------
__global__ __launch_bounds__(128) void out_kernel(
    const float* __restrict__ right, const float* __restrict__ scale_post_p,
    const float* __restrict__ b1, const float* __restrict__ b2,
    float* __restrict__ out, int n_right)
{
    __shared__ __align__(16) float Hs[OROWS][2 * EMB];
    __shared__ __align__(16) float Us[OROWS][EMB];
    const int j = threadIdx.x;
    const int row0 = blockIdx.x * OROWS;
    const float sp = scale_post_p[0];

    for (int i = threadIdx.x; i < OROWS * 64; i += 128) {
        const int r = i >> 6;
        const int c4 = i & 63;
        const int row = row0 + r;
        float4 v = make_float4(0.f, 0.f, 0.f, 0.f);
        if (row < n_right) {
            if (c4 < 32) {
                v = ((const float4*)(g_conv + (size_t)row * EMB))[c4];
                v.x *= sp; v.y *= sp; v.z *= sp; v.w *= sp;
            } else {
                v = ((const float4*)(right + (size_t)row * EMB))[c4 - 32];
            }
        }
        ((float4*)Hs[r])[c4] = v;
    }
    __syncthreads();

    ull acc[OROWS];
    const float b1j = b1[j];
#pragma unroll
    for (int r = 0; r < OROWS; r++) acc[r] = pk2(b1j, 0.f);
    const ull* __restrict__ W1P = (const ull*)g_W1P;
#pragma unroll 1
    for (int k4 = 0; k4 < 64; k4++) {
        const ull wa = W1P[(size_t)(2 * k4) * EMB + j];
        const ull wb = W1P[(size_t)(2 * k4 + 1) * EMB + j];
#pragma unroll
        for (int r = 0; r < OROWS; r++) {
            const ulonglong2 x = ((const ulonglong2*)Hs[r])[k4];
            FMA2(acc[r], wa, x.x);
            FMA2(acc[r], wb, x.y);
        }
    }
#pragma unroll
    for (int r = 0; r < OROWS; r++) Us[r][j] = fmaxf(upk_sum(acc[r]), 0.f);
    __syncthreads();

    ull acc2[OROWS];
    const float b2j = b2[j];
#pragma unroll
    for (int r = 0; r < OROWS; r++) acc2[r] = pk2(b2j, 0.f);
    const ull* __restrict__ W2P = (const ull*)g_W2P;
#pragma unroll 1
    for (int k4 = 0; k4 < 32; k4++) {
        const ull wa = W2P[(size_t)(2 * k4) * EMB + j];
        const ull wb = W2P[(size_t)(2 * k4 + 1) * EMB + j];
#pragma unroll
        for (int r = 0; r < OROWS; r++) {
            const ulonglong2 x = ((const ulonglong2*)Us[r])[k4];
            FMA2(acc2[r], wa, x.x);
            FMA2(acc2[r], wb, x.y);
        }
    }
#pragma unroll
    for (int r = 0; r < OROWS; r++) {
        const int row = row0 + r;
        if (row < n_right) out[(size_t)row * EMB + j] = upk_sum(acc2[r]);
    }
}

// ---------------------------------------------------------------------------
extern "C" void kernel_launch(void* const* d_in, const int* in_sizes, int n_in,
                              void* d_out, int out_size)
{
    const float* left   = (const float*)d_in[0];
    const void*  eidx   = d_in[1];
    const float* ef     = (const float*)d_in[2];
    const float* right  = (const float*)d_in[3];
    // d_in[4] = scatter_out_size scalar (derived from right_features instead)
    const float* W_left      = (const float*)d_in[5];
    const float* b_left      = (const float*)d_in[6];
    const float* W_edge      = (const float*)d_in[7];
    const float* W_right     = (const float*)d_in[8];
    const float* scale_final = (const float*)d_in[9];
    const float* W_final     = (const float*)d_in[10];
    const float* b_final     = (const float*)d_in[11];
    const float* scale_post  = (const float*)d_in[12];
    const float* W_out1      = (const float*)d_in[13];
    const float* b_out1      = (const float*)d_in[14];
    const float* W_out2      = (const float*)d_in[15];
    const float* b_out2      = (const float*)d_in[16];

    const int n_left  = in_sizes[0] / EMB;
    const int n_edges = in_sizes[2];          // edge_features count (EDGE_FEAT=1)
    const int n_right = in_sizes[3] / EMB;

    // launch 0: index-width detection
    detect_idx_kernel<<<1, 32>>>((const long long*)eidx, n_edges);

    // launch 1: zero conv + build paired weights
    const int n4 = n_right * EMB / 4;
    const int prep_blocks = (n4 + 255) / 256;
    prep_kernel<<<prep_blocks, 256>>>(W_left, W_right, W_final, W_out1, W_out2, n4);

    // launch 2: merged projections
    const int blocksL = (n_left + 63) / 64;
    const int blocksR = (n_right + 63) / 64;
    proj_kernel<<<blocksL + blocksR, 128>>>(left, right, b_left, n_left, n_right, blocksL);

    // launch 3: fused edge stage (gather -> GEMM -> scatter)
    edge_kernel<<<(n_edges + ETILE - 1) / ETILE, 128>>>(
        eidx, ef, W_edge, b_final, scale_final, n_edges);

    // launch 4: output MLP
    out_kernel<<<(n_right + OROWS - 1) / OROWS, 128>>>(
        right, scale_post, b_out1, b_out2, (float*)d_out, n_right);
}

// round 5
// speedup vs baseline: 1.6964x; 1.6964x over previous
#include <cuda_runtime.h>

#define EMB 128
#define OROWS 16
#define PROWS 8
#define MAXNODES 100000

// Scratch (device globals: no allocations allowed in kernel_launch)
__device__ __align__(128) float g_Lp[MAXNODES * EMB];
__device__ __align__(128) float g_Rp[MAXNODES * EMB];
__device__ __align__(128) float g_acc[MAXNODES * EMB];   // sum of relu'd joints per right node
__device__ __align__(128) float g_deg[MAXNODES];         // edge count per right node
__device__ __align__(128) float g_WLT[EMB * EMB];        // W_left^T
__device__ __align__(128) float g_WRT[EMB * EMB];        // W_right^T
__device__ __align__(128) float g_WfT[EMB * EMB];        // W_final^T
__device__ __align__(128) float g_W1T[2 * EMB * EMB];    // W_out1^T
__device__ __align__(128) float g_W2T[EMB * EMB];        // W_out2^T
__device__ int g_is64;

__device__ __forceinline__ void red_add_v4(float* p, float4 v) {
    asm volatile("red.global.add.v4.f32 [%0], {%1, %2, %3, %4};"
                 :: "l"(p), "f"(v.x), "f"(v.y), "f"(v.z), "f"(v.w) : "memory");
}
__device__ __forceinline__ void red_add_f32(float* p, float v) {
    asm volatile("red.global.add.f32 [%0], %1;" :: "l"(p), "f"(v) : "memory");
}

// ---------------------------------------------------------------------------
// Detect whether edge_indices buffer is int64 or int32 (JAX x64-off pitfall).
// ---------------------------------------------------------------------------
__global__ void detect_idx_kernel(const long long* __restrict__ e, int n64_safe) {
    if (blockIdx.x == 0 && threadIdx.x == 0) {
        int m = n64_safe < 64 ? n64_safe : 64;
        int ok = 1;
        for (int i = 0; i < m; i++) {
            long long v = e[i];
            if (v < 0 || v >= (1LL << 31)) { ok = 0; break; }
        }
        g_is64 = ok;
    }
}

// ---------------------------------------------------------------------------
// prep: zero g_acc + g_deg, transpose all weight matrices (coalesced writes).
// ---------------------------------------------------------------------------
__global__ void prep_kernel(const float* __restrict__ Wl, const float* __restrict__ Wr,
                            const float* __restrict__ Wf, const float* __restrict__ W1,
                            const float* __restrict__ W2, int n4, int n_right) {
    const int idx = blockIdx.x * blockDim.x + threadIdx.x;
    if (idx < n4) ((float4*)g_acc)[idx] = make_float4(0.f, 0.f, 0.f, 0.f);
    if (idx < n_right) g_deg[idx] = 0.f;
    if (idx < EMB * EMB) {
        const int k = idx >> 7, j = idx & 127;
        g_WLT[idx] = Wl[j * EMB + k];
        g_WRT[idx] = Wr[j * EMB + k];
        g_WfT[idx] = Wf[j * EMB + k];
        g_W2T[idx] = W2[j * EMB + k];
    }
    if (idx < 2 * EMB * EMB) {
        const int k = idx >> 7, j = idx & 127;
        g_W1T[idx] = W1[j * 2 * EMB + k];  // W1: [128][256] -> W1T: [256][128]
    }
}

// ---------------------------------------------------------------------------
// Merged projections: out[m,j] = sum_k A[m,k] * W[j,k] (+ b[j] for left side)
// Thread j owns column j; W^T loads are warp-coalesced.
// ---------------------------------------------------------------------------
__global__ __launch_bounds__(128) void proj_kernel(
    const float* __restrict__ left, const float* __restrict__ right,
    const float* __restrict__ bL, int n_left, int n_right, int blocksL)
{
    __shared__ __align__(16) float As[PROWS][EMB];
    const int j = threadIdx.x;

    const float* __restrict__ A;
    const float* __restrict__ WT;
    float* out; int n; float bj; int row0;
    if (blockIdx.x < blocksL) {
        A = left; WT = g_WLT; out = g_Lp; n = n_left;
        bj = bL[j]; row0 = blockIdx.x * 64;
    } else {
        A = right; WT = g_WRT; out = g_Rp; n = n_right;
        bj = 0.f; row0 = (blockIdx.x - blocksL) * 64;
    }

    for (int rt = 0; rt < 64; rt += PROWS) {
        const int rbase = row0 + rt;
        __syncthreads();
        for (int i = threadIdx.x; i < PROWS * 32; i += 128) {
            const int r = i >> 5, c4 = i & 31;
            float4 v = make_float4(0.f, 0.f, 0.f, 0.f);
            if (rbase + r < n)
                v = ((const float4*)(A + (size_t)(rbase + r) * EMB))[c4];
            ((float4*)As[r])[c4] = v;
        }
        __syncthreads();

        float acc[PROWS];
#pragma unroll
        for (int r = 0; r < PROWS; r++) acc[r] = bj;

#pragma unroll 2
        for (int k4 = 0; k4 < 32; k4++) {
            const float* __restrict__ wp = WT + (size_t)(k4 * 4) * EMB + j;
            const float w0 = wp[0];
            const float w1 = wp[EMB];
            const float w2 = wp[2 * EMB];
            const float w3 = wp[3 * EMB];
#pragma unroll
            for (int r = 0; r < PROWS; r++) {
                const float4 x = ((const float4*)As[r])[k4];
                acc[r] = fmaf(w0, x.x, acc[r]);
                acc[r] = fmaf(w1, x.y, acc[r]);
                acc[r] = fmaf(w2, x.z, acc[r]);
                acc[r] = fmaf(w3, x.w, acc[r]);
            }
        }
#pragma unroll
        for (int r = 0; r < PROWS; r++)
            if (rbase + r < n) out[(size_t)(rbase + r) * EMB + j] = acc[r];
    }
}

// ---------------------------------------------------------------------------
// Edge stage (GEMM commuted out!): t = relu((Lp[s]+Rp[d]+ef*we)*scale);
// red.v4 t into g_acc[d]; count degree. One warp per edge, 8 edges/block.
// ---------------------------------------------------------------------------
__global__ __launch_bounds__(256) void edge_kernel(
    const void* __restrict__ eidx_raw, const float* __restrict__ ef,
    const float* __restrict__ wedge, const float* __restrict__ scale_p,
    int n_edges)
{
    const int warp = threadIdx.x >> 5, lane = threadIdx.x & 31;
    const int ge = blockIdx.x * 8 + warp;
    if (ge >= n_edges) return;

    const int is64 = g_is64;
    int s, d;
    if (is64) {
        const long long* __restrict__ e64 = (const long long*)eidx_raw;
        s = (int)e64[ge]; d = (int)e64[n_edges + ge];
    } else {
        const int* __restrict__ e32 = (const int*)eidx_raw;
        s = e32[ge]; d = e32[n_edges + ge];
    }
    const float fe = ef[ge];
    const float scale = scale_p[0];

    const float4 we = ((const float4*)wedge)[lane];
    const float4 l = ((const float4*)(g_Lp + (size_t)s * EMB))[lane];
    const float4 r = ((const float4*)(g_Rp + (size_t)d * EMB))[lane];

    float4 t;
    t.x = fmaxf(fmaf(fe, we.x, l.x + r.x) * scale, 0.f);
    t.y = fmaxf(fmaf(fe, we.y, l.y + r.y) * scale, 0.f);
    t.z = fmaxf(fmaf(fe, we.z, l.z + r.z) * scale, 0.f);
    t.w = fmaxf(fmaf(fe, we.w, l.w + r.w) * scale, 0.f);

    red_add_v4(&g_acc[(size_t)d * EMB + lane * 4], t);
    if (lane == 0) red_add_f32(&g_deg[d], 1.0f);
}

// ---------------------------------------------------------------------------
// Fused conv + output MLP:
//   conv[r] = g_acc[r] @ Wf^T + deg[r]*b_final      (the commuted edge GEMM)
//   h = [conv*scale_post ; right]; u = relu(h@W1^T+b1); out = u@W2^T+b2
// 128 threads, OROWS rows per block, coalesced W^T loads.
// ---------------------------------------------------------------------------
__global__ __launch_bounds__(128) void out_kernel(
    const float* __restrict__ right, const float* __restrict__ scale_post_p,
    const float* __restrict__ bf, const float* __restrict__ b1,
    const float* __restrict__ b2, float* __restrict__ out, int n_right)
{
    __shared__ __align__(16) float AccS[OROWS][EMB];
    __shared__ __align__(16) float Hs[OROWS][2 * EMB];
    __shared__ __align__(16) float Us[OROWS][EMB];
    __shared__ float Dg[OROWS];
    const int j = threadIdx.x;
    const int row0 = blockIdx.x * OROWS;
    const float sp = scale_post_p[0];

    // load acc tile + degree + right half of h
    for (int i = threadIdx.x; i < OROWS * 32; i += 128) {
        const int r = i >> 5, c4 = i & 31;
        const int row = row0 + r;
        float4 a = make_float4(0.f, 0.f, 0.f, 0.f);
        float4 v = make_float4(0.f, 0.f, 0.f, 0.f);
        if (row < n_right) {
            a = ((const float4*)(g_acc + (size_t)row * EMB))[c4];
            v = ((const float4*)(right + (size_t)row * EMB))[c4];
        }
        ((float4*)AccS[r])[c4] = a;
        ((float4*)(Hs[r] + EMB))[c4] = v;
    }
    if (threadIdx.x < OROWS) {
        const int row = row0 + threadIdx.x;
        Dg[threadIdx.x] = (row < n_right) ? g_deg[row] : 0.f;
    }
    __syncthreads();

    // Stage 0: conv[r][j] = acc[r] . WfT[:,j] + deg[r]*bf[j]; Hs[r][j] = conv*sp
    {
        float acc[OROWS];
        const float bfj = bf[j];
#pragma unroll
        for (int r = 0; r < OROWS; r++) acc[r] = Dg[r] * bfj;
#pragma unroll 1
        for (int k4 = 0; k4 < 32; k4++) {
            const float* __restrict__ wp = g_WfT + (size_t)(k4 * 4) * EMB + j;
            const float w0 = wp[0];
            const float w1 = wp[EMB];
            const float w2 = wp[2 * EMB];
            const float w3 = wp[3 * EMB];
#pragma unroll
            for (int r = 0; r < OROWS; r++) {
                const float4 x = ((const float4*)AccS[r])[k4];
                acc[r] = fmaf(w0, x.x, acc[r]);
                acc[r] = fmaf(w1, x.y, acc[r]);
                acc[r] = fmaf(w2, x.z, acc[r]);
                acc[r] = fmaf(w3, x.w, acc[r]);
            }
        }
#pragma unroll
        for (int r = 0; r < OROWS; r++) Hs[r][j] = acc[r] * sp;
    }
    __syncthreads();

    // Stage 1: u = relu(h @ W1^T + b1)
    {
        float acc[OROWS];
        const float b1j = b1[j];
#pragma unroll
        for (int r = 0; r < OROWS; r++) acc[r] = b1j;
#pragma unroll 1
        for (int k4 = 0; k4 < 64; k4++) {
            const float* __restrict__ wp = g_W1T + (size_t)(k4 * 4) * EMB + j;
            const float w0 = wp[0];
            const float w1 = wp[EMB];
            const float w2 = wp[2 * EMB];
            const float w3 = wp[3 * EMB];
#pragma unroll
            for (int r = 0; r < OROWS; r++) {
                const float4 x = ((const float4*)Hs[r])[k4];
                acc[r] = fmaf(w0, x.x, acc[r]);
                acc[r] = fmaf(w1, x.y, acc[r]);
                acc[r] = fmaf(w2, x.z, acc[r]);
                acc[r] = fmaf(w3, x.w, acc[r]);
            }
        }
#pragma unroll
        for (int r = 0; r < OROWS; r++) Us[r][j] = fmaxf(acc[r], 0.f);
    }
    __syncthreads();

    // Stage 2: out = u @ W2^T + b2
    {
        float acc2[OROWS];
        const float b2j = b2[j];
#pragma unroll
        for (int r = 0; r < OROWS; r++) acc2[r] = b2j;
#pragma unroll 1
        for (int k4 = 0; k4 < 32; k4++) {
            const float* __restrict__ wp = g_W2T + (size_t)(k4 * 4) * EMB + j;
            const float w0 = wp[0];
            const float w1 = wp[EMB];
            const float w2 = wp[2 * EMB];
            const float w3 = wp[3 * EMB];
#pragma unroll
            for (int r = 0; r < OROWS; r++) {
                const float4 x = ((const float4*)Us[r])[k4];
                acc2[r] = fmaf(w0, x.x, acc2[r]);
                acc2[r] = fmaf(w1, x.y, acc2[r]);
                acc2[r] = fmaf(w2, x.z, acc2[r]);
                acc2[r] = fmaf(w3, x.w, acc2[r]);
            }
        }
#pragma unroll
        for (int r = 0; r < OROWS; r++) {
            const int row = row0 + r;
            if (row < n_right) out[(size_t)row * EMB + j] = acc2[r];
        }
    }
}

// ---------------------------------------------------------------------------
extern "C" void kernel_launch(void* const* d_in, const int* in_sizes, int n_in,
                              void* d_out, int out_size)
{
    const float* left   = (const float*)d_in[0];
    const void*  eidx   = d_in[1];
    const float* ef     = (const float*)d_in[2];
    const float* right  = (const float*)d_in[3];
    // d_in[4] = scatter_out_size scalar (derived from right_features instead)
    const float* W_left      = (const float*)d_in[5];
    const float* b_left      = (const float*)d_in[6];
    const float* W_edge      = (const float*)d_in[7];
    const float* W_right     = (const float*)d_in[8];
    const float* scale_final = (const float*)d_in[9];
    const float* W_final     = (const float*)d_in[10];
    const float* b_final     = (const float*)d_in[11];
    const float* scale_post  = (const float*)d_in[12];
    const float* W_out1      = (const float*)d_in[13];
    const float* b_out1      = (const float*)d_in[14];
    const float* W_out2      = (const float*)d_in[15];
    const float* b_out2      = (const float*)d_in[16];

    const int n_left  = in_sizes[0] / EMB;
    const int n_edges = in_sizes[2];          // edge_features count (EDGE_FEAT=1)
    const int n_right = in_sizes[3] / EMB;

    // launch 0: index-width detection
    detect_idx_kernel<<<1, 32>>>((const long long*)eidx, n_edges);

    // launch 1: zero accumulators + transpose weights
    const int n4 = n_right * EMB / 4;
    prep_kernel<<<(n4 + 255) / 256, 256>>>(W_left, W_right, W_final, W_out1,
                                           W_out2, n4, n_right);

    // launch 2: merged projections
    const int blocksL = (n_left + 63) / 64;
    const int blocksR = (n_right + 63) / 64;
    proj_kernel<<<blocksL + blocksR, 128>>>(left, right, b_left, n_left, n_right, blocksL);

    // launch 3: edge gather-combine-relu-scatter (no GEMM; it commutes out)
    edge_kernel<<<(n_edges + 7) / 8, 256>>>(eidx, ef, W_edge, scale_final, n_edges);

    // launch 4: fused conv GEMM + output MLP
    out_kernel<<<(n_right + OROWS - 1) / OROWS, 128>>>(
        right, scale_post, b_final, b_out1, b_out2, (float*)d_out, n_right);
}

// round 7
// speedup vs baseline: 1.7165x; 1.0118x over previous
#include <cuda_runtime.h>
#include <cstdint>

#define EMB 132  // careful: EMB used below must be 128; use S for stride
#undef EMB
#define EMB 128
#define ASTRIDE 132
#define MAXNODES 100000

// Scratch (device globals: no allocations allowed in kernel_launch)
__device__ __align__(128) float g_Lp[MAXNODES * EMB];
__device__ __align__(128) float g_Rp[MAXNODES * EMB];
__device__ __align__(128) float g_acc[MAXNODES * EMB];
__device__ __align__(128) float g_deg[MAXNODES];
__device__ __align__(128) float g_Wc[EMB * EMB];     // sp * (W1a @ Wf)
__device__ __align__(128) float g_bvec[EMB];         // sp * (W1a @ bf)
// fragment-packed hi/lo weights: [m][(ks*16+nt)*32+lane] = {b0h,b1h,b0l,b1l}
// m: 0=W_left 1=W_right 2=Wc 3=W1b 4=W_out2
__device__ __align__(128) float4 g_frag[5][16384];
__device__ int g_is64;

// ---------------- helpers ----------------
__device__ __forceinline__ uint32_t tf32r(float v) {
    uint32_t r;
    asm("cvt.rna.tf32.f32 %0, %1;" : "=r"(r) : "f"(v));
    return r;
}
__device__ __forceinline__ void mma8(float* c, uint32_t a0, uint32_t a1,
                                     uint32_t a2, uint32_t a3,
                                     uint32_t b0, uint32_t b1) {
    asm volatile(
        "mma.sync.aligned.m16n8k8.row.col.f32.tf32.tf32.f32 "
        "{%0,%1,%2,%3}, {%4,%5,%6,%7}, {%8,%9}, {%0,%1,%2,%3};"
        : "+f"(c[0]), "+f"(c[1]), "+f"(c[2]), "+f"(c[3])
        : "r"(a0), "r"(a1), "r"(a2), "r"(a3), "r"(b0), "r"(b1));
}
__device__ __forceinline__ void red_add_v4(float* p, float4 v) {
    asm volatile("red.global.add.v4.f32 [%0], {%1, %2, %3, %4};"
                 :: "l"(p), "f"(v.x), "f"(v.y), "f"(v.z), "f"(v.w) : "memory");
}
__device__ __forceinline__ void red_add_f32(float* p, float v) {
    asm volatile("red.global.add.f32 [%0], %1;" :: "l"(p), "f"(v) : "memory");
}

// ---------------------------------------------------------------------------
// 128x128x128 compensated-TF32 GEMM on mma.sync. 256 threads / 8 warps;
// warp w owns rows 16w..16w+15, all 128 cols (16 n-tiles).
// As: smem, raw f32, ASTRIDE-padded. Bf: fragment-packed weights (global).
// acc[16][4] accumulates (caller inits / chains).
// ---------------------------------------------------------------------------
__device__ __forceinline__ void gemm128(const float* __restrict__ As,
                                        const float4* __restrict__ Bf,
                                        float acc[16][4], int warp, int lane) {
    const int g = lane >> 2, t = lane & 3;
    const float* r0 = As + (warp * 16 + g) * ASTRIDE;
    const float* r8 = r0 + 8 * ASTRIDE;
#pragma unroll
    for (int ks = 0; ks < 16; ks++) {
        const int k = ks * 8 + t;
        const float a0 = r0[k], a1 = r8[k], a2 = r0[k + 4], a3 = r8[k + 4];
        const uint32_t a0h = tf32r(a0), a1h = tf32r(a1);
        const uint32_t a2h = tf32r(a2), a3h = tf32r(a3);
        const uint32_t a0l = tf32r(a0 - __uint_as_float(a0h));
        const uint32_t a1l = tf32r(a1 - __uint_as_float(a1h));
        const uint32_t a2l = tf32r(a2 - __uint_as_float(a2h));
        const uint32_t a3l = tf32r(a3 - __uint_as_float(a3h));
        const float4* bp = Bf + ks * 512 + lane;
#pragma unroll
        for (int nt = 0; nt < 16; nt++) {
            const float4 b = bp[nt * 32];
            const uint32_t b0h = __float_as_uint(b.x), b1h = __float_as_uint(b.y);
            const uint32_t b0l = __float_as_uint(b.z), b1l = __float_as_uint(b.w);
            mma8(acc[nt], a0h, a1h, a2h, a3h, b0h, b1h);
            mma8(acc[nt], a0l, a1l, a2l, a3l, b0h, b1h);
            mma8(acc[nt], a0h, a1h, a2h, a3h, b0l, b1l);
        }
    }
}

// stage 128 rows of a row-major [n, 128] matrix into padded smem (zero-fill OOB)
__device__ __forceinline__ void stage_rows(const float* __restrict__ gptr, int row0,
                                           int n, float* As, int tid) {
    for (int i = tid; i < 128 * 32; i += 256) {
        const int r = i >> 5, c4 = i & 31;
        float4 v = make_float4(0.f, 0.f, 0.f, 0.f);
        if (row0 + r < n)
            v = ((const float4*)(gptr + (size_t)(row0 + r) * EMB))[c4];
        *(float4*)(As + r * ASTRIDE + c4 * 4) = v;
    }
}

// ---------------------------------------------------------------------------
// Detect whether edge_indices buffer is int64 or int32 (JAX x64-off pitfall).
// ---------------------------------------------------------------------------
__global__ void detect_idx_kernel(const long long* __restrict__ e, int n64_safe) {
    if (blockIdx.x == 0 && threadIdx.x == 0) {
        int m = n64_safe < 64 ? n64_safe : 64;
        int ok = 1;
        for (int i = 0; i < m; i++) {
            long long v = e[i];
            if (v < 0 || v >= (1LL << 31)) { ok = 0; break; }
        }
        g_is64 = ok;
    }
}

// ---------------------------------------------------------------------------
// prep1: zero g_acc/g_deg; Wc = sp*(W1a@Wf); bvec = sp*(W1a@bf).
// ---------------------------------------------------------------------------
__global__ void prep1_kernel(const float* __restrict__ Wf, const float* __restrict__ W1,
                             const float* __restrict__ bf, const float* __restrict__ sp_p,
                             int n4, int n_right) {
    const int idx = blockIdx.x * blockDim.x + threadIdx.x;
    if (idx < n4) ((float4*)g_acc)[idx] = make_float4(0.f, 0.f, 0.f, 0.f);
    if (idx < n_right) g_deg[idx] = 0.f;
    if (idx < EMB * EMB) {
        const int j = idx >> 7, k = idx & 127;
        float s = 0.f;
        for (int m = 0; m < EMB; m++)
            s = fmaf(W1[j * 2 * EMB + m], Wf[m * EMB + k], s);
        g_Wc[idx] = s * sp_p[0];
    }
    if (idx < EMB) {
        float s = 0.f;
        for (int m = 0; m < EMB; m++)
            s = fmaf(W1[idx * 2 * EMB + m], bf[m], s);
        g_bvec[idx] = s * sp_p[0];
    }
}

// ---------------------------------------------------------------------------
// prep2: pack fragment-ordered hi/lo tf32 weights.
// frag[(ks*16+nt)*32+lane] = {hi(W[n][k0]), hi(W[n][k1]), lo0, lo1}
//   n = nt*8 + lane/4, k0 = ks*8 + lane%4, k1 = k0+4
// ---------------------------------------------------------------------------
__global__ void prep2_kernel(const float* __restrict__ Wl, const float* __restrict__ Wr,
                             const float* __restrict__ W1, const float* __restrict__ W2) {
    const int idx = blockIdx.x * blockDim.x + threadIdx.x;
    if (idx >= 5 * 16384) return;
    const int m = idx >> 14, r = idx & 16383;
    const int lane = r & 31, nt = (r >> 5) & 15, ks = r >> 9;
    const int g = lane >> 2, t = lane & 3;
    const int n = nt * 8 + g, k0 = ks * 8 + t;

    const float* src; int L, off;
    switch (m) {
        case 0:  src = Wl;   L = EMB;     off = 0;   break;
        case 1:  src = Wr;   L = EMB;     off = 0;   break;
        case 2:  src = g_Wc; L = EMB;     off = 0;   break;
        case 3:  src = W1;   L = 2 * EMB; off = EMB; break;
        default: src = W2;   L = EMB;     off = 0;   break;
    }
    const float v0 = src[n * L + off + k0];
    const float v1 = src[n * L + off + k0 + 4];
    const uint32_t h0 = tf32r(v0), h1 = tf32r(v1);
    const uint32_t l0 = tf32r(v0 - __uint_as_float(h0));
    const uint32_t l1 = tf32r(v1 - __uint_as_float(h1));
    g_frag[m][r] = make_float4(__uint_as_float(h0), __uint_as_float(h1),
                               __uint_as_float(l0), __uint_as_float(l1));
}

// ---------------------------------------------------------------------------
// Tensor-core projections: Lp = left@WL^T + bL ; Rp = right@WR^T
// ---------------------------------------------------------------------------
__global__ __launch_bounds__(256) void proj_mma(
    const float* __restrict__ left, const float* __restrict__ right,
    const float* __restrict__ bL, int n_left, int n_right, int blocksL)
{
    extern __shared__ float sm[];
    float* As = sm;
    float* sBias = sm + 128 * ASTRIDE;
    const int tid = threadIdx.x, warp = tid >> 5, lane = tid & 31;

    const float* A; const float4* Bf; float* outp; int n, row0;
    if ((int)blockIdx.x < blocksL) {
        A = left;  Bf = g_frag[0]; outp = g_Lp; n = n_left;
        row0 = blockIdx.x * 128;
        if (tid < 128) sBias[tid] = bL[tid];
    } else {
        A = right; Bf = g_frag[1]; outp = g_Rp; n = n_right;
        row0 = (blockIdx.x - blocksL) * 128;
        if (tid < 128) sBias[tid] = 0.f;
    }
    stage_rows(A, row0, n, As, tid);
    __syncthreads();

    float acc[16][4];
#pragma unroll
    for (int nt = 0; nt < 16; nt++)
#pragma unroll
        for (int i = 0; i < 4; i++) acc[nt][i] = 0.f;

    gemm128(As, Bf, acc, warp, lane);

    const int g = lane >> 2, t = lane & 3;
    const int r0 = row0 + warp * 16 + g, r1 = r0 + 8;
#pragma unroll
    for (int nt = 0; nt < 16; nt++) {
        const int c = nt * 8 + 2 * t;
        if (r0 < n) {
            float2 o = make_float2(acc[nt][0] + sBias[c], acc[nt][1] + sBias[c + 1]);
            *(float2*)(outp + (size_t)r0 * EMB + c) = o;
        }
        if (r1 < n) {
            float2 o = make_float2(acc[nt][2] + sBias[c], acc[nt][3] + sBias[c + 1]);
            *(float2*)(outp + (size_t)r1 * EMB + c) = o;
        }
    }
}

// ---------------------------------------------------------------------------
// Edge stage (GEMM commuted out): t = relu((Lp[s]+Rp[d]+ef*we)*scale);
// red.v4 into g_acc[d]; count degree. One warp per edge.
// ---------------------------------------------------------------------------
__global__ __launch_bounds__(256) void edge_kernel(
    const void* __restrict__ eidx_raw, const float* __restrict__ ef,
    const float* __restrict__ wedge, const float* __restrict__ scale_p,
    int n_edges)
{
    const int warp = threadIdx.x >> 5, lane = threadIdx.x & 31;
    const int ge = blockIdx.x * 8 + warp;
    if (ge >= n_edges) return;

    int s, d;
    if (g_is64) {
        const long long* __restrict__ e64 = (const long long*)eidx_raw;
        s = (int)e64[ge]; d = (int)e64[n_edges + ge];
    } else {
        const int* __restrict__ e32 = (const int*)eidx_raw;
        s = e32[ge]; d = e32[n_edges + ge];
    }
    const float fe = ef[ge];
    const float scale = scale_p[0];

    const float4 we = ((const float4*)wedge)[lane];
    const float4 l = ((const float4*)(g_Lp + (size_t)s * EMB))[lane];
    const float4 r = ((const float4*)(g_Rp + (size_t)d * EMB))[lane];

    float4 t;
    t.x = fmaxf(fmaf(fe, we.x, l.x + r.x) * scale, 0.f);
    t.y = fmaxf(fmaf(fe, we.y, l.y + r.y) * scale, 0.f);
    t.z = fmaxf(fmaf(fe, we.z, l.z + r.z) * scale, 0.f);
    t.w = fmaxf(fmaf(fe, we.w, l.w + r.w) * scale, 0.f);

    red_add_v4(&g_acc[(size_t)d * EMB + lane * 4], t);
    if (lane == 0) red_add_f32(&g_deg[d], 1.0f);
}

// ---------------------------------------------------------------------------
// Fused output: u = relu(acc@Wc^T + deg*bvec + right@W1b^T + b1);
//               out = u@W2^T + b2.   (Wf GEMM folded into Wc at prep.)
// ---------------------------------------------------------------------------
__global__ __launch_bounds__(256) void out_mma(
    const float* __restrict__ right, const float* __restrict__ b1,
    const float* __restrict__ b2, float* __restrict__ out, int n_right)
{
    extern __shared__ float sm[];
    float* As = sm;                        // acc tile, later u tile
    float* Rs = sm + 128 * ASTRIDE;        // right tile
    float* sBv = sm + 2 * 128 * ASTRIDE;   // bvec
    float* sB1 = sBv + 128;
    float* sB2 = sB1 + 128;
    const int tid = threadIdx.x, warp = tid >> 5, lane = tid & 31;
    const int row0 = blockIdx.x * 128;

    if (tid < 128) {
        sBv[tid] = g_bvec[tid];
        sB1[tid] = b1[tid];
        sB2[tid] = b2[tid];
    }
    stage_rows(g_acc, row0, n_right, As, tid);
    stage_rows(right, row0, n_right, Rs, tid);
    __syncthreads();

    float acc[16][4];
#pragma unroll
    for (int nt = 0; nt < 16; nt++)
#pragma unroll
        for (int i = 0; i < 4; i++) acc[nt][i] = 0.f;

    gemm128(As, g_frag[2], acc, warp, lane);   // acc_tile @ Wc^T
    gemm128(Rs, g_frag[3], acc, warp, lane);   // + right @ W1b^T

    const int g = lane >> 2, t = lane & 3;
    const int sr0 = warp * 16 + g, sr1 = sr0 + 8;
    const float d0 = (row0 + sr0 < n_right) ? g_deg[row0 + sr0] : 0.f;
    const float d1 = (row0 + sr1 < n_right) ? g_deg[row0 + sr1] : 0.f;
    __syncthreads();   // all warps done reading As before overwrite

#pragma unroll
    for (int nt = 0; nt < 16; nt++) {
        const int c = nt * 8 + 2 * t;
        As[sr0 * ASTRIDE + c]     = fmaxf(acc[nt][0] + d0 * sBv[c]     + sB1[c],     0.f);
        As[sr0 * ASTRIDE + c + 1] = fmaxf(acc[nt][1] + d0 * sBv[c + 1] + sB1[c + 1], 0.f);
        As[sr1 * ASTRIDE + c]     = fmaxf(acc[nt][2] + d1 * sBv[c]     + sB1[c],     0.f);
        As[sr1 * ASTRIDE + c + 1] = fmaxf(acc[nt][3] + d1 * sBv[c + 1] + sB1[c + 1], 0.f);
    }
    __syncthreads();

#pragma unroll
    for (int nt = 0; nt < 16; nt++)
#pragma unroll
        for (int i = 0; i < 4; i++) acc[nt][i] = 0.f;

    gemm128(As, g_frag[4], acc, warp, lane);   // u @ W2^T

    const int r0g = row0 + sr0, r1g = row0 + sr1;
#pragma unroll
    for (int nt = 0; nt < 16; nt++) {
        const int c = nt * 8 + 2 * t;
        if (r0g < n_right) {
            float2 o = make_float2(acc[nt][0] + sB2[c], acc[nt][1] + sB2[c + 1]);
            *(float2*)(out + (size_t)r0g * EMB + c) = o;
        }
        if (r1g < n_right) {
            float2 o = make_float2(acc[nt][2] + sB2[c], acc[nt][3] + sB2[c + 1]);
            *(float2*)(out + (size_t)r1g * EMB + c) = o;
        }
    }
}

// ---------------------------------------------------------------------------
extern "C" void kernel_launch(void* const* d_in, const int* in_sizes, int n_in,
                              void* d_out, int out_size)
{
    const float* left   = (const float*)d_in[0];
    const void*  eidx   = d_in[1];
    const float* ef     = (const float*)d_in[2];
    const float* right  = (const float*)d_in[3];
    // d_in[4] = scatter_out_size scalar (derived from right_features instead)
    const float* W_left      = (const float*)d_in[5];
    const float* b_left      = (const float*)d_in[6];
    const float* W_edge      = (const float*)d_in[7];
    const float* W_right     = (const float*)d_in[8];
    const float* scale_final = (const float*)d_in[9];
    const float* W_final     = (const float*)d_in[10];
    const float* b_final     = (const float*)d_in[11];
    const float* scale_post  = (const float*)d_in[12];
    const float* W_out1      = (const float*)d_in[13];
    const float* b_out1      = (const float*)d_in[14];
    const float* W_out2      = (const float*)d_in[15];
    const float* b_out2      = (const float*)d_in[16];

    const int n_left  = in_sizes[0] / EMB;
    const int n_edges = in_sizes[2];          // edge_features count (EDGE_FEAT=1)
    const int n_right = in_sizes[3] / EMB;

    const int SM_PROJ = (128 * ASTRIDE + 128) * (int)sizeof(float);
    const int SM_OUT  = (2 * 128 * ASTRIDE + 3 * 128) * (int)sizeof(float);
    cudaFuncSetAttribute(proj_mma, cudaFuncAttributeMaxDynamicSharedMemorySize, SM_PROJ);
    cudaFuncSetAttribute(out_mma,  cudaFuncAttributeMaxDynamicSharedMemorySize, SM_OUT);

    // launch 0: index-width detection
    detect_idx_kernel<<<1, 32>>>((const long long*)eidx, n_edges);

    // launch 1: zero accumulators + folded weight Wc/bvec
    const int n4 = n_right * EMB / 4;
    prep1_kernel<<<(n4 + 255) / 256, 256>>>(W_final, W_out1, b_final, scale_post,
                                            n4, n_right);

    // launch 2: fragment-pack all weights (hi/lo tf32)
    prep2_kernel<<<(5 * 16384 + 255) / 256, 256>>>(W_left, W_right, W_out1, W_out2);

    // launch 3: tensor-core projections
    const int blocksL = (n_left + 127) / 128;
    const int blocksR = (n_right + 127) / 128;
    proj_mma<<<blocksL + blocksR, 256, SM_PROJ>>>(left, right, b_left,
                                                  n_left, n_right, blocksL);

    // launch 4: edge gather-combine-relu-scatter
    edge_kernel<<<(n_edges + 7) / 8, 256>>>(eidx, ef, W_edge, scale_final, n_edges);

    // launch 5: fused output MLP (Wf folded into Wc)
    out_mma<<<(n_right + 127) / 128, 256, SM_OUT>>>(right, b_out1, b_out2,
                                                    (float*)d_out, n_right);
}

// round 8
// speedup vs baseline: 1.7181x; 1.0010x over previous
#include <cuda_runtime.h>
#include <cstdint>

#define EMB 128
#define ASTRIDE 132
#define MAXNODES 100000

// Scratch (device globals: no allocations allowed in kernel_launch)
__device__ __align__(128) float g_Lp[MAXNODES * EMB];
__device__ __align__(128) float g_Rp[MAXNODES * EMB];
__device__ __align__(128) float g_acc[MAXNODES * EMB];
__device__ __align__(128) float g_deg[MAXNODES];
__device__ __align__(128) float g_Wc[EMB * EMB];     // sp * (W1a @ Wf)
__device__ __align__(128) float g_bvec[EMB];         // sp * (W1a @ bf)
// fragment-packed hi/lo weights: [m][(ks*16+nt)*32+lane] = {b0h,b1h,b0l,b1l}
// m: 0=W_left 1=W_right 2=Wc 3=W1b 4=W_out2
__device__ __align__(128) float4 g_frag[5][16384];
__device__ int g_is64;

// ---------------- helpers ----------------
__device__ __forceinline__ uint32_t tf32r(float v) {
    uint32_t r;
    asm("cvt.rna.tf32.f32 %0, %1;" : "=r"(r) : "f"(v));
    return r;
}
__device__ __forceinline__ void mma8(float* c, uint32_t a0, uint32_t a1,
                                     uint32_t a2, uint32_t a3,
                                     uint32_t b0, uint32_t b1) {
    asm volatile(
        "mma.sync.aligned.m16n8k8.row.col.f32.tf32.tf32.f32 "
        "{%0,%1,%2,%3}, {%4,%5,%6,%7}, {%8,%9}, {%0,%1,%2,%3};"
        : "+f"(c[0]), "+f"(c[1]), "+f"(c[2]), "+f"(c[3])
        : "r"(a0), "r"(a1), "r"(a2), "r"(a3), "r"(b0), "r"(b1));
}
__device__ __forceinline__ void red_add_v4(float* p, float4 v) {
    asm volatile("red.global.add.v4.f32 [%0], {%1, %2, %3, %4};"
                 :: "l"(p), "f"(v.x), "f"(v.y), "f"(v.z), "f"(v.w) : "memory");
}
__device__ __forceinline__ void red_add_f32(float* p, float v) {
    asm volatile("red.global.add.f32 [%0], %1;" :: "l"(p), "f"(v) : "memory");
}

// ---------------------------------------------------------------------------
// 128x128x128 compensated-TF32 GEMM, 512 threads / 16 warps.
// Warp (rg, ch): rows rg*16..+15, cols ch*64..+63 (8 n-tiles). acc[8][4].
// As: smem, raw f32, ASTRIDE-padded. Bf: fragment-packed weights (global/L2).
// ---------------------------------------------------------------------------
__device__ __forceinline__ void gemm128h(const float* __restrict__ As,
                                         const float4* __restrict__ Bf,
                                         float acc[8][4], int rg, int ch, int lane) {
    const int g = lane >> 2, t = lane & 3;
    const float* r0 = As + (rg * 16 + g) * ASTRIDE;
    const float* r8 = r0 + 8 * ASTRIDE;
#pragma unroll
    for (int ks = 0; ks < 16; ks++) {
        const int k = ks * 8 + t;
        const float a0 = r0[k], a1 = r8[k], a2 = r0[k + 4], a3 = r8[k + 4];
        const uint32_t a0h = tf32r(a0), a1h = tf32r(a1);
        const uint32_t a2h = tf32r(a2), a3h = tf32r(a3);
        const uint32_t a0l = tf32r(a0 - __uint_as_float(a0h));
        const uint32_t a1l = tf32r(a1 - __uint_as_float(a1h));
        const uint32_t a2l = tf32r(a2 - __uint_as_float(a2h));
        const uint32_t a3l = tf32r(a3 - __uint_as_float(a3h));
        const float4* bp = Bf + ks * 512 + ch * 256 + lane;
#pragma unroll
        for (int nt = 0; nt < 8; nt++) {
            const float4 b = bp[nt * 32];
            const uint32_t b0h = __float_as_uint(b.x), b1h = __float_as_uint(b.y);
            const uint32_t b0l = __float_as_uint(b.z), b1l = __float_as_uint(b.w);
            mma8(acc[nt], a0h, a1h, a2h, a3h, b0h, b1h);
            mma8(acc[nt], a0l, a1l, a2l, a3l, b0h, b1h);
            mma8(acc[nt], a0h, a1h, a2h, a3h, b0l, b1l);
        }
    }
}

// stage 128 rows of a row-major [n, 128] matrix into padded smem (zero-fill OOB)
__device__ __forceinline__ void stage_rows(const float* __restrict__ gptr, int row0,
                                           int n, float* As, int tid, int nthr) {
    for (int i = tid; i < 128 * 32; i += nthr) {
        const int r = i >> 5, c4 = i & 31;
        float4 v = make_float4(0.f, 0.f, 0.f, 0.f);
        if (row0 + r < n)
            v = ((const float4*)(gptr + (size_t)(row0 + r) * EMB))[c4];
        *(float4*)(As + r * ASTRIDE + c4 * 4) = v;
    }
}

// ---------------------------------------------------------------------------
// Detect whether edge_indices buffer is int64 or int32 (JAX x64-off pitfall).
// ---------------------------------------------------------------------------
__global__ void detect_idx_kernel(const long long* __restrict__ e, int n64_safe) {
    if (blockIdx.x == 0 && threadIdx.x == 0) {
        int m = n64_safe < 64 ? n64_safe : 64;
        int ok = 1;
        for (int i = 0; i < m; i++) {
            long long v = e[i];
            if (v < 0 || v >= (1LL << 31)) { ok = 0; break; }
        }
        g_is64 = ok;
    }
}

// ---------------------------------------------------------------------------
// prep1: zero g_acc/g_deg; Wc = sp*(W1a@Wf); bvec = sp*(W1a@bf).
// ---------------------------------------------------------------------------
__global__ void prep1_kernel(const float* __restrict__ Wf, const float* __restrict__ W1,
                             const float* __restrict__ bf, const float* __restrict__ sp_p,
                             int n4, int n_right) {
    const int idx = blockIdx.x * blockDim.x + threadIdx.x;
    if (idx < n4) ((float4*)g_acc)[idx] = make_float4(0.f, 0.f, 0.f, 0.f);
    if (idx < n_right) g_deg[idx] = 0.f;
    if (idx < EMB * EMB) {
        const int j = idx >> 7, k = idx & 127;
        float s = 0.f;
        for (int m = 0; m < EMB; m++)
            s = fmaf(W1[j * 2 * EMB + m], Wf[m * EMB + k], s);
        g_Wc[idx] = s * sp_p[0];
    }
    if (idx < EMB) {
        float s = 0.f;
        for (int m = 0; m < EMB; m++)
            s = fmaf(W1[idx * 2 * EMB + m], bf[m], s);
        g_bvec[idx] = s * sp_p[0];
    }
}

// ---------------------------------------------------------------------------
// prep2: pack fragment-ordered hi/lo tf32 weights.
// frag[(ks*16+nt)*32+lane] = {hi(W[n][k0]), hi(W[n][k1]), lo0, lo1}
//   n = nt*8 + lane/4, k0 = ks*8 + lane%4, k1 = k0+4
// ---------------------------------------------------------------------------
__global__ void prep2_kernel(const float* __restrict__ Wl, const float* __restrict__ Wr,
                             const float* __restrict__ W1, const float* __restrict__ W2) {
    const int idx = blockIdx.x * blockDim.x + threadIdx.x;
    if (idx >= 5 * 16384) return;
    const int m = idx >> 14, r = idx & 16383;
    const int lane = r & 31, nt = (r >> 5) & 15, ks = r >> 9;
    const int g = lane >> 2, t = lane & 3;
    const int n = nt * 8 + g, k0 = ks * 8 + t;

    const float* src; int L, off;
    switch (m) {
        case 0:  src = Wl;   L = EMB;     off = 0;   break;
        case 1:  src = Wr;   L = EMB;     off = 0;   break;
        case 2:  src = g_Wc; L = EMB;     off = 0;   break;
        case 3:  src = W1;   L = 2 * EMB; off = EMB; break;
        default: src = W2;   L = EMB;     off = 0;   break;
    }
    const float v0 = src[n * L + off + k0];
    const float v1 = src[n * L + off + k0 + 4];
    const uint32_t h0 = tf32r(v0), h1 = tf32r(v1);
    const uint32_t l0 = tf32r(v0 - __uint_as_float(h0));
    const uint32_t l1 = tf32r(v1 - __uint_as_float(h1));
    g_frag[m][r] = make_float4(__uint_as_float(h0), __uint_as_float(h1),
                               __uint_as_float(l0), __uint_as_float(l1));
}

// ---------------------------------------------------------------------------
// Tensor-core projections: Lp = left@WL^T + bL ; Rp = right@WR^T
// 512 threads, 16 warps; warp (rg, ch) tile = 16 rows x 64 cols.
// ---------------------------------------------------------------------------
__global__ __launch_bounds__(512) void proj_mma(
    const float* __restrict__ left, const float* __restrict__ right,
    const float* __restrict__ bL, int n_left, int n_right, int blocksL)
{
    extern __shared__ float sm[];
    float* As = sm;
    float* sBias = sm + 128 * ASTRIDE;
    const int tid = threadIdx.x, warp = tid >> 5, lane = tid & 31;
    const int rg = warp >> 1, ch = warp & 1;

    const float* A; const float4* Bf; float* outp; int n, row0;
    if ((int)blockIdx.x < blocksL) {
        A = left;  Bf = g_frag[0]; outp = g_Lp; n = n_left;
        row0 = blockIdx.x * 128;
        if (tid < 128) sBias[tid] = bL[tid];
    } else {
        A = right; Bf = g_frag[1]; outp = g_Rp; n = n_right;
        row0 = (blockIdx.x - blocksL) * 128;
        if (tid < 128) sBias[tid] = 0.f;
    }
    stage_rows(A, row0, n, As, tid, 512);
    __syncthreads();

    float acc[8][4];
#pragma unroll
    for (int nt = 0; nt < 8; nt++)
#pragma unroll
        for (int i = 0; i < 4; i++) acc[nt][i] = 0.f;

    gemm128h(As, Bf, acc, rg, ch, lane);

    const int g = lane >> 2, t = lane & 3;
    const int r0 = row0 + rg * 16 + g, r1 = r0 + 8;
#pragma unroll
    for (int nt = 0; nt < 8; nt++) {
        const int c = (ch * 8 + nt) * 8 + 2 * t;
        if (r0 < n) {
            float2 o = make_float2(acc[nt][0] + sBias[c], acc[nt][1] + sBias[c + 1]);
            *(float2*)(outp + (size_t)r0 * EMB + c) = o;
        }
        if (r1 < n) {
            float2 o = make_float2(acc[nt][2] + sBias[c], acc[nt][3] + sBias[c + 1]);
            *(float2*)(outp + (size_t)r1 * EMB + c) = o;
        }
    }
}

// ---------------------------------------------------------------------------
// Edge stage (GEMM commuted out): t = relu((Lp[s]+Rp[d]+ef*we)*scale);
// red.v4 into g_acc[d]; count degree. One warp per edge.
// ---------------------------------------------------------------------------
__global__ __launch_bounds__(256) void edge_kernel(
    const void* __restrict__ eidx_raw, const float* __restrict__ ef,
    const float* __restrict__ wedge, const float* __restrict__ scale_p,
    int n_edges)
{
    const int warp = threadIdx.x >> 5, lane = threadIdx.x & 31;
    const int ge = blockIdx.x * 8 + warp;
    if (ge >= n_edges) return;

    int s, d;
    if (g_is64) {
        const long long* __restrict__ e64 = (const long long*)eidx_raw;
        s = (int)e64[ge]; d = (int)e64[n_edges + ge];
    } else {
        const int* __restrict__ e32 = (const int*)eidx_raw;
        s = e32[ge]; d = e32[n_edges + ge];
    }
    const float fe = ef[ge];
    const float scale = scale_p[0];

    const float4 we = ((const float4*)wedge)[lane];
    const float4 l = ((const float4*)(g_Lp + (size_t)s * EMB))[lane];
    const float4 r = ((const float4*)(g_Rp + (size_t)d * EMB))[lane];

    float4 t;
    t.x = fmaxf(fmaf(fe, we.x, l.x + r.x) * scale, 0.f);
    t.y = fmaxf(fmaf(fe, we.y, l.y + r.y) * scale, 0.f);
    t.z = fmaxf(fmaf(fe, we.z, l.z + r.z) * scale, 0.f);
    t.w = fmaxf(fmaf(fe, we.w, l.w + r.w) * scale, 0.f);

    red_add_v4(&g_acc[(size_t)d * EMB + lane * 4], t);
    if (lane == 0) red_add_f32(&g_deg[d], 1.0f);
}

// ---------------------------------------------------------------------------
// Fused output: u = relu(acc@Wc^T + deg*bvec + right@W1b^T + b1);
//               out = u@W2^T + b2.   (Wf GEMM folded into Wc at prep.)
// 512 threads, 16 warps.
// ---------------------------------------------------------------------------
__global__ __launch_bounds__(512) void out_mma(
    const float* __restrict__ right, const float* __restrict__ b1,
    const float* __restrict__ b2, float* __restrict__ out, int n_right)
{
    extern __shared__ float sm[];
    float* As = sm;                        // acc tile, later u tile
    float* Rs = sm + 128 * ASTRIDE;        // right tile
    float* sBv = sm + 2 * 128 * ASTRIDE;   // bvec
    float* sB1 = sBv + 128;
    float* sB2 = sB1 + 128;
    const int tid = threadIdx.x, warp = tid >> 5, lane = tid & 31;
    const int rg = warp >> 1, ch = warp & 1;
    const int row0 = blockIdx.x * 128;

    if (tid < 128) {
        sBv[tid] = g_bvec[tid];
        sB1[tid] = b1[tid];
        sB2[tid] = b2[tid];
    }
    stage_rows(g_acc, row0, n_right, As, tid, 512);
    stage_rows(right, row0, n_right, Rs, tid, 512);
    __syncthreads();

    float acc[8][4];
#pragma unroll
    for (int nt = 0; nt < 8; nt++)
#pragma unroll
        for (int i = 0; i < 4; i++) acc[nt][i] = 0.f;

    gemm128h(As, g_frag[2], acc, rg, ch, lane);   // acc_tile @ Wc^T
    gemm128h(Rs, g_frag[3], acc, rg, ch, lane);   // + right @ W1b^T

    const int g = lane >> 2, t = lane & 3;
    const int sr0 = rg * 16 + g, sr1 = sr0 + 8;
    const float d0 = (row0 + sr0 < n_right) ? g_deg[row0 + sr0] : 0.f;
    const float d1 = (row0 + sr1 < n_right) ? g_deg[row0 + sr1] : 0.f;
    __syncthreads();   // all warps done reading As before overwrite

#pragma unroll
    for (int nt = 0; nt < 8; nt++) {
        const int c = (ch * 8 + nt) * 8 + 2 * t;
        As[sr0 * ASTRIDE + c]     = fmaxf(acc[nt][0] + d0 * sBv[c]     + sB1[c],     0.f);
        As[sr0 * ASTRIDE + c + 1] = fmaxf(acc[nt][1] + d0 * sBv[c + 1] + sB1[c + 1], 0.f);
        As[sr1 * ASTRIDE + c]     = fmaxf(acc[nt][2] + d1 * sBv[c]     + sB1[c],     0.f);
        As[sr1 * ASTRIDE + c + 1] = fmaxf(acc[nt][3] + d1 * sBv[c + 1] + sB1[c + 1], 0.f);
    }
    __syncthreads();

#pragma unroll
    for (int nt = 0; nt < 8; nt++)
#pragma unroll
        for (int i = 0; i < 4; i++) acc[nt][i] = 0.f;

    gemm128h(As, g_frag[4], acc, rg, ch, lane);   // u @ W2^T

    const int r0g = row0 + sr0, r1g = row0 + sr1;
#pragma unroll
    for (int nt = 0; nt < 8; nt++) {
        const int c = (ch * 8 + nt) * 8 + 2 * t;
        if (r0g < n_right) {
            float2 o = make_float2(acc[nt][0] + sB2[c], acc[nt][1] + sB2[c + 1]);
            *(float2*)(out + (size_t)r0g * EMB + c) = o;
        }
        if (r1g < n_right) {
            float2 o = make_float2(acc[nt][2] + sB2[c], acc[nt][3] + sB2[c + 1]);
            *(float2*)(out + (size_t)r1g * EMB + c) = o;
        }
    }
}

// ---------------------------------------------------------------------------
extern "C" void kernel_launch(void* const* d_in, const int* in_sizes, int n_in,
                              void* d_out, int out_size)
{
    const float* left   = (const float*)d_in[0];
    const void*  eidx   = d_in[1];
    const float* ef     = (const float*)d_in[2];
    const float* right  = (const float*)d_in[3];
    // d_in[4] = scatter_out_size scalar (derived from right_features instead)
    const float* W_left      = (const float*)d_in[5];
    const float* b_left      = (const float*)d_in[6];
    const float* W_edge      = (const float*)d_in[7];
    const float* W_right     = (const float*)d_in[8];
    const float* scale_final = (const float*)d_in[9];
    const float* W_final     = (const float*)d_in[10];
    const float* b_final     = (const float*)d_in[11];
    const float* scale_post  = (const float*)d_in[12];
    const float* W_out1      = (const float*)d_in[13];
    const float* b_out1      = (const float*)d_in[14];
    const float* W_out2      = (const float*)d_in[15];
    const float* b_out2      = (const float*)d_in[16];

    const int n_left  = in_sizes[0] / EMB;
    const int n_edges = in_sizes[2];          // edge_features count (EDGE_FEAT=1)
    const int n_right = in_sizes[3] / EMB;

    const int SM_PROJ = (128 * ASTRIDE + 128) * (int)sizeof(float);
    const int SM_OUT  = (2 * 128 * ASTRIDE + 3 * 128) * (int)sizeof(float);
    cudaFuncSetAttribute(proj_mma, cudaFuncAttributeMaxDynamicSharedMemorySize, SM_PROJ);
    cudaFuncSetAttribute(out_mma,  cudaFuncAttributeMaxDynamicSharedMemorySize, SM_OUT);

    // launch 0: index-width detection
    detect_idx_kernel<<<1, 32>>>((const long long*)eidx, n_edges);

    // launch 1: zero accumulators + folded weight Wc/bvec
    const int n4 = n_right * EMB / 4;
    prep1_kernel<<<(n4 + 255) / 256, 256>>>(W_final, W_out1, b_final, scale_post,
                                            n4, n_right);

    // launch 2: fragment-pack all weights (hi/lo tf32)
    prep2_kernel<<<(5 * 16384 + 255) / 256, 256>>>(W_left, W_right, W_out1, W_out2);

    // launch 3: tensor-core projections
    const int blocksL = (n_left + 127) / 128;
    const int blocksR = (n_right + 127) / 128;
    proj_mma<<<blocksL + blocksR, 512, SM_PROJ>>>(left, right, b_left,
                                                  n_left, n_right, blocksL);

    // launch 4: edge gather-combine-relu-scatter
    edge_kernel<<<(n_edges + 7) / 8, 256>>>(eidx, ef, W_edge, scale_final, n_edges);

    // launch 5: fused output MLP (Wf folded into Wc)
    out_mma<<<(n_right + 127) / 128, 512, SM_OUT>>>(right, b_out1, b_out2,
                                                    (float*)d_out, n_right);
}

// round 9
// speedup vs baseline: 3.1163x; 1.8138x over previous
#include <cuda_runtime.h>
#include <cstdint>

#define EMB 128
#define ASTRIDE 132
#define TROWS 64
#define MAXNODES 100000

// Scratch (device globals: no allocations allowed in kernel_launch)
__device__ __align__(128) float g_Lp[MAXNODES * EMB];
__device__ __align__(128) float g_Rp[MAXNODES * EMB];
__device__ __align__(128) float g_acc[MAXNODES * EMB];
__device__ __align__(128) float g_deg[MAXNODES];
__device__ __align__(128) float g_Wc[EMB * EMB];     // sp * (W1a @ Wf)
__device__ __align__(128) float g_bvec[EMB];         // sp * (W1a @ bf)
// fragment-packed hi/lo weights: [m][(ks*16+nt)*32+lane] = {b0h,b1h,b0l,b1l}
// m: 0=W_left 1=W_right 2=Wc 3=W1b 4=W_out2
__device__ __align__(128) float4 g_frag[5][8192];
__device__ int g_is64;

// ---------------- helpers ----------------
__device__ __forceinline__ uint32_t tf32r(float v) {
    uint32_t r;
    asm("cvt.rna.tf32.f32 %0, %1;" : "=r"(r) : "f"(v));
    return r;
}
__device__ __forceinline__ void mma8(float* c, uint32_t a0, uint32_t a1,
                                     uint32_t a2, uint32_t a3,
                                     uint32_t b0, uint32_t b1) {
    asm volatile(
        "mma.sync.aligned.m16n8k8.row.col.f32.tf32.tf32.f32 "
        "{%0,%1,%2,%3}, {%4,%5,%6,%7}, {%8,%9}, {%0,%1,%2,%3};"
        : "+f"(c[0]), "+f"(c[1]), "+f"(c[2]), "+f"(c[3])
        : "r"(a0), "r"(a1), "r"(a2), "r"(a3), "r"(b0), "r"(b1));
}
__device__ __forceinline__ void red_add_v4(float* p, float4 v) {
    asm volatile("red.global.add.v4.f32 [%0], {%1, %2, %3, %4};"
                 :: "l"(p), "f"(v.x), "f"(v.y), "f"(v.z), "f"(v.w) : "memory");
}
__device__ __forceinline__ void red_add_f32(float* p, float v) {
    asm volatile("red.global.add.f32 [%0], %1;" :: "l"(p), "f"(v) : "memory");
}

// ---------------------------------------------------------------------------
// 64x128x128 compensated-TF32 GEMM, 256 threads / 8 warps.
// Warp (rg, ch): rows rg*16..+15, cols ch*64..+63 (8 n-tiles). acc[8][4].
// As: smem, raw f32, ASTRIDE-padded. Bf: fragment-packed weights (global/L2).
// ---------------------------------------------------------------------------
__device__ __forceinline__ void gemm64(const float* __restrict__ As,
                                       const float4* __restrict__ Bf,
                                       float acc[8][4], int rg, int ch, int lane) {
    const int g = lane >> 2, t = lane & 3;
    const float* r0 = As + (rg * 16 + g) * ASTRIDE;
    const float* r8 = r0 + 8 * ASTRIDE;
#pragma unroll
    for (int ks = 0; ks < 16; ks++) {
        const int k = ks * 8 + t;
        const float a0 = r0[k], a1 = r8[k], a2 = r0[k + 4], a3 = r8[k + 4];
        const uint32_t a0h = tf32r(a0), a1h = tf32r(a1);
        const uint32_t a2h = tf32r(a2), a3h = tf32r(a3);
        const uint32_t a0l = tf32r(a0 - __uint_as_float(a0h));
        const uint32_t a1l = tf32r(a1 - __uint_as_float(a1h));
        const uint32_t a2l = tf32r(a2 - __uint_as_float(a2h));
        const uint32_t a3l = tf32r(a3 - __uint_as_float(a3h));
        const float4* bp = Bf + ks * 512 + ch * 256 + lane;
#pragma unroll
        for (int nt = 0; nt < 8; nt++) {
            const float4 b = bp[nt * 32];
            const uint32_t b0h = __float_as_uint(b.x), b1h = __float_as_uint(b.y);
            const uint32_t b0l = __float_as_uint(b.z), b1l = __float_as_uint(b.w);
            mma8(acc[nt], a0h, a1h, a2h, a3h, b0h, b1h);
            mma8(acc[nt], a0l, a1l, a2l, a3l, b0h, b1h);
            mma8(acc[nt], a0h, a1h, a2h, a3h, b0l, b1l);
        }
    }
}

// stage TROWS rows of a row-major [n, 128] matrix into padded smem (zero-fill OOB)
__device__ __forceinline__ void stage_rows(const float* __restrict__ gptr, int row0,
                                           int n, float* As, int tid) {
    for (int i = tid; i < TROWS * 32; i += 256) {
        const int r = i >> 5, c4 = i & 31;
        float4 v = make_float4(0.f, 0.f, 0.f, 0.f);
        if (row0 + r < n)
            v = ((const float4*)(gptr + (size_t)(row0 + r) * EMB))[c4];
        *(float4*)(As + r * ASTRIDE + c4 * 4) = v;
    }
}

// ---------------------------------------------------------------------------
// Detect whether edge_indices buffer is int64 or int32 (JAX x64-off pitfall).
// ---------------------------------------------------------------------------
__global__ void detect_idx_kernel(const long long* __restrict__ e, int n64_safe) {
    if (blockIdx.x == 0 && threadIdx.x == 0) {
        int m = n64_safe < 64 ? n64_safe : 64;
        int ok = 1;
        for (int i = 0; i < m; i++) {
            long long v = e[i];
            if (v < 0 || v >= (1LL << 31)) { ok = 0; break; }
        }
        g_is64 = ok;
    }
}

// ---------------------------------------------------------------------------
// prep1: zero g_acc/g_deg; Wc = sp*(W1a@Wf); bvec = sp*(W1a@bf).
// ---------------------------------------------------------------------------
__global__ void prep1_kernel(const float* __restrict__ Wf, const float* __restrict__ W1,
                             const float* __restrict__ bf, const float* __restrict__ sp_p,
                             int n4, int n_right) {
    const int idx = blockIdx.x * blockDim.x + threadIdx.x;
    if (idx < n4) ((float4*)g_acc)[idx] = make_float4(0.f, 0.f, 0.f, 0.f);
    if (idx < n_right) g_deg[idx] = 0.f;
    if (idx < EMB * EMB) {
        const int j = idx >> 7, k = idx & 127;
        float s = 0.f;
        for (int m = 0; m < EMB; m++)
            s = fmaf(W1[j * 2 * EMB + m], Wf[m * EMB + k], s);
        g_Wc[idx] = s * sp_p[0];
    }
    if (idx < EMB) {
        float s = 0.f;
        for (int m = 0; m < EMB; m++)
            s = fmaf(W1[idx * 2 * EMB + m], bf[m], s);
        g_bvec[idx] = s * sp_p[0];
    }
}

// ---------------------------------------------------------------------------
// prep2: pack fragment-ordered hi/lo tf32 weights.
// frag[(ks*16+nt)*32+lane] = {hi(W[n][k0]), hi(W[n][k1]), lo0, lo1}
//   n = nt*8 + lane/4, k0 = ks*8 + lane%4, k1 = k0+4
// ---------------------------------------------------------------------------
__global__ void prep2_kernel(const float* __restrict__ Wl, const float* __restrict__ Wr,
                             const float* __restrict__ W1, const float* __restrict__ W2) {
    const int idx = blockIdx.x * blockDim.x + threadIdx.x;
    if (idx >= 5 * 8192) return;
    const int m = idx >> 13, r = idx & 8191;
    const int lane = r & 31, nt = (r >> 5) & 15, ks = r >> 9;   // ks in [0,16)
    const int g = lane >> 2, t = lane & 3;
    const int n = nt * 8 + g, k0 = ks * 8 + t;

    const float* src; int L, off;
    switch (m) {
        case 0:  src = Wl;   L = EMB;     off = 0;   break;
        case 1:  src = Wr;   L = EMB;     off = 0;   break;
        case 2:  src = g_Wc; L = EMB;     off = 0;   break;
        case 3:  src = W1;   L = 2 * EMB; off = EMB; break;
        default: src = W2;   L = EMB;     off = 0;   break;
    }
    const float v0 = src[n * L + off + k0];
    const float v1 = src[n * L + off + k0 + 4];
    const uint32_t h0 = tf32r(v0), h1 = tf32r(v1);
    const uint32_t l0 = tf32r(v0 - __uint_as_float(h0));
    const uint32_t l1 = tf32r(v1 - __uint_as_float(h1));
    g_frag[m][r] = make_float4(__uint_as_float(h0), __uint_as_float(h1),
                               __uint_as_float(l0), __uint_as_float(l1));
}

// ---------------------------------------------------------------------------
// Tensor-core projections: Lp = left@WL^T + bL ; Rp = right@WR^T
// 256 threads / 8 warps; block tile = 64 rows, warp tile = 16 x 64.
// ---------------------------------------------------------------------------
__global__ __launch_bounds__(256) void proj_mma(
    const float* __restrict__ left, const float* __restrict__ right,
    const float* __restrict__ bL, int n_left, int n_right, int blocksL)
{
    extern __shared__ float sm[];
    float* As = sm;
    float* sBias = sm + TROWS * ASTRIDE;
    const int tid = threadIdx.x, warp = tid >> 5, lane = tid & 31;
    const int rg = warp >> 1, ch = warp & 1;

    const float* A; const float4* Bf; float* outp; int n, row0;
    if ((int)blockIdx.x < blocksL) {
        A = left;  Bf = g_frag[0]; outp = g_Lp; n = n_left;
        row0 = blockIdx.x * TROWS;
        if (tid < 128) sBias[tid] = bL[tid];
    } else {
        A = right; Bf = g_frag[1]; outp = g_Rp; n = n_right;
        row0 = (blockIdx.x - blocksL) * TROWS;
        if (tid < 128) sBias[tid] = 0.f;
    }
    stage_rows(A, row0, n, As, tid);
    __syncthreads();

    float acc[8][4];
#pragma unroll
    for (int nt = 0; nt < 8; nt++)
#pragma unroll
        for (int i = 0; i < 4; i++) acc[nt][i] = 0.f;

    gemm64(As, Bf, acc, rg, ch, lane);

    const int g = lane >> 2, t = lane & 3;
    const int r0 = row0 + rg * 16 + g, r1 = r0 + 8;
#pragma unroll
    for (int nt = 0; nt < 8; nt++) {
        const int c = (ch * 8 + nt) * 8 + 2 * t;
        if (r0 < n) {
            float2 o = make_float2(acc[nt][0] + sBias[c], acc[nt][1] + sBias[c + 1]);
            *(float2*)(outp + (size_t)r0 * EMB + c) = o;
        }
        if (r1 < n) {
            float2 o = make_float2(acc[nt][2] + sBias[c], acc[nt][3] + sBias[c + 1]);
            *(float2*)(outp + (size_t)r1 * EMB + c) = o;
        }
    }
}

// ---------------------------------------------------------------------------
// Edge stage (GEMM commuted out): t = relu((Lp[s]+Rp[d]+ef*we)*scale);
// red.v4 into g_acc[d]; count degree. One warp per edge.
// ---------------------------------------------------------------------------
__global__ __launch_bounds__(256) void edge_kernel(
    const void* __restrict__ eidx_raw, const float* __restrict__ ef,
    const float* __restrict__ wedge, const float* __restrict__ scale_p,
    int n_edges)
{
    const int warp = threadIdx.x >> 5, lane = threadIdx.x & 31;
    const int ge = blockIdx.x * 8 + warp;
    if (ge >= n_edges) return;

    int s, d;
    if (g_is64) {
        const long long* __restrict__ e64 = (const long long*)eidx_raw;
        s = (int)e64[ge]; d = (int)e64[n_edges + ge];
    } else {
        const int* __restrict__ e32 = (const int*)eidx_raw;
        s = e32[ge]; d = e32[n_edges + ge];
    }
    const float fe = ef[ge];
    const float scale = scale_p[0];

    const float4 we = ((const float4*)wedge)[lane];
    const float4 l = ((const float4*)(g_Lp + (size_t)s * EMB))[lane];
    const float4 r = ((const float4*)(g_Rp + (size_t)d * EMB))[lane];

    float4 t;
    t.x = fmaxf(fmaf(fe, we.x, l.x + r.x) * scale, 0.f);
    t.y = fmaxf(fmaf(fe, we.y, l.y + r.y) * scale, 0.f);
    t.z = fmaxf(fmaf(fe, we.z, l.z + r.z) * scale, 0.f);
    t.w = fmaxf(fmaf(fe, we.w, l.w + r.w) * scale, 0.f);

    red_add_v4(&g_acc[(size_t)d * EMB + lane * 4], t);
    if (lane == 0) red_add_f32(&g_deg[d], 1.0f);
}

// ---------------------------------------------------------------------------
// Fused output: u = relu(acc@Wc^T + deg*bvec + right@W1b^T + b1);
//               out = u@W2^T + b2.   (Wf folded into Wc at prep.)
// 256 threads / 8 warps; 64-row tile; ONE shared A buffer reused across
// the three GEMM phases (acc tile -> right tile -> u tile).
// ---------------------------------------------------------------------------
__global__ __launch_bounds__(256) void out_mma(
    const float* __restrict__ right, const float* __restrict__ b1,
    const float* __restrict__ b2, float* __restrict__ out, int n_right)
{
    extern __shared__ float sm[];
    float* As = sm;
    float* sBv = sm + TROWS * ASTRIDE;
    float* sB1 = sBv + 128;
    float* sB2 = sB1 + 128;
    const int tid = threadIdx.x, warp = tid >> 5, lane = tid & 31;
    const int rg = warp >> 1, ch = warp & 1;
    const int row0 = blockIdx.x * TROWS;

    if (tid < 128) {
        sBv[tid] = g_bvec[tid];
        sB1[tid] = b1[tid];
        sB2[tid] = b2[tid];
    }

    float acc[8][4];
#pragma unroll
    for (int nt = 0; nt < 8; nt++)
#pragma unroll
        for (int i = 0; i < 4; i++) acc[nt][i] = 0.f;

    // Phase 1: acc_tile @ Wc^T
    stage_rows(g_acc, row0, n_right, As, tid);
    __syncthreads();
    gemm64(As, g_frag[2], acc, rg, ch, lane);
    __syncthreads();   // everyone done reading As

    // Phase 2: + right @ W1b^T
    stage_rows(right, row0, n_right, As, tid);
    __syncthreads();
    gemm64(As, g_frag[3], acc, rg, ch, lane);

    const int g = lane >> 2, t = lane & 3;
    const int sr0 = rg * 16 + g, sr1 = sr0 + 8;
    const float d0 = (row0 + sr0 < n_right) ? g_deg[row0 + sr0] : 0.f;
    const float d1 = (row0 + sr1 < n_right) ? g_deg[row0 + sr1] : 0.f;
    __syncthreads();   // everyone done reading As

    // u = relu(acc + deg*bvec + b1) -> As
#pragma unroll
    for (int nt = 0; nt < 8; nt++) {
        const int c = (ch * 8 + nt) * 8 + 2 * t;
        As[sr0 * ASTRIDE + c]     = fmaxf(acc[nt][0] + d0 * sBv[c]     + sB1[c],     0.f);
        As[sr0 * ASTRIDE + c + 1] = fmaxf(acc[nt][1] + d0 * sBv[c + 1] + sB1[c + 1], 0.f);
        As[sr1 * ASTRIDE + c]     = fmaxf(acc[nt][2] + d1 * sBv[c]     + sB1[c],     0.f);
        As[sr1 * ASTRIDE + c + 1] = fmaxf(acc[nt][3] + d1 * sBv[c + 1] + sB1[c + 1], 0.f);
    }
    __syncthreads();

    // Phase 3: u @ W2^T
#pragma unroll
    for (int nt = 0; nt < 8; nt++)
#pragma unroll
        for (int i = 0; i < 4; i++) acc[nt][i] = 0.f;

    gemm64(As, g_frag[4], acc, rg, ch, lane);

    const int r0g = row0 + sr0, r1g = row0 + sr1;
#pragma unroll
    for (int nt = 0; nt < 8; nt++) {
        const int c = (ch * 8 + nt) * 8 + 2 * t;
        if (r0g < n_right) {
            float2 o = make_float2(acc[nt][0] + sB2[c], acc[nt][1] + sB2[c + 1]);
            *(float2*)(out + (size_t)r0g * EMB + c) = o;
        }
        if (r1g < n_right) {
            float2 o = make_float2(acc[nt][2] + sB2[c], acc[nt][3] + sB2[c + 1]);
            *(float2*)(out + (size_t)r1g * EMB + c) = o;
        }
    }
}

// ---------------------------------------------------------------------------
extern "C" void kernel_launch(void* const* d_in, const int* in_sizes, int n_in,
                              void* d_out, int out_size)
{
    const float* left   = (const float*)d_in[0];
    const void*  eidx   = d_in[1];
    const float* ef     = (const float*)d_in[2];
    const float* right  = (const float*)d_in[3];
    // d_in[4] = scatter_out_size scalar (derived from right_features instead)
    const float* W_left      = (const float*)d_in[5];
    const float* b_left      = (const float*)d_in[6];
    const float* W_edge      = (const float*)d_in[7];
    const float* W_right     = (const float*)d_in[8];
    const float* scale_final = (const float*)d_in[9];
    const float* W_final     = (const float*)d_in[10];
    const float* b_final     = (const float*)d_in[11];
    const float* scale_post  = (const float*)d_in[12];
    const float* W_out1      = (const float*)d_in[13];
    const float* b_out1      = (const float*)d_in[14];
    const float* W_out2      = (const float*)d_in[15];
    const float* b_out2      = (const float*)d_in[16];

    const int n_left  = in_sizes[0] / EMB;
    const int n_edges = in_sizes[2];          // edge_features count (EDGE_FEAT=1)
    const int n_right = in_sizes[3] / EMB;

    const int SM_PROJ = (TROWS * ASTRIDE + 128) * (int)sizeof(float);
    const int SM_OUT  = (TROWS * ASTRIDE + 3 * 128) * (int)sizeof(float);
    cudaFuncSetAttribute(proj_mma, cudaFuncAttributeMaxDynamicSharedMemorySize, SM_PROJ);
    cudaFuncSetAttribute(out_mma,  cudaFuncAttributeMaxDynamicSharedMemorySize, SM_OUT);

    // launch 0: index-width detection
    detect_idx_kernel<<<1, 32>>>((const long long*)eidx, n_edges);

    // launch 1: zero accumulators + folded weight Wc/bvec
    const int n4 = n_right * EMB / 4;
    prep1_kernel<<<(n4 + 255) / 256, 256>>>(W_final, W_out1, b_final, scale_post,
                                            n4, n_right);

    // launch 2: fragment-pack all weights (hi/lo tf32)
    prep2_kernel<<<(5 * 8192 + 255) / 256, 256>>>(W_left, W_right, W_out1, W_out2);

    // launch 3: tensor-core projections
    const int blocksL = (n_left + TROWS - 1) / TROWS;
    const int blocksR = (n_right + TROWS - 1) / TROWS;
    proj_mma<<<blocksL + blocksR, 256, SM_PROJ>>>(left, right, b_left,
                                                  n_left, n_right, blocksL);

    // launch 4: edge gather-combine-relu-scatter
    edge_kernel<<<(n_edges + 7) / 8, 256>>>(eidx, ef, W_edge, scale_final, n_edges);

    // launch 5: fused output MLP (Wf folded into Wc)
    out_mma<<<(n_right + TROWS - 1) / TROWS, 256, SM_OUT>>>(right, b_out1, b_out2,
                                                            (float*)d_out, n_right);
}

// round 10
// speedup vs baseline: 3.7622x; 1.2073x over previous
#include <cuda_runtime.h>
#include <cstdint>

#define EMB 128
#define ASTRIDE 132
#define TROWS 64
#define MAXNODES 100000

// Scratch (device globals: no allocations allowed in kernel_launch)
__device__ __align__(128) float g_Lp[MAXNODES * EMB];
__device__ __align__(128) float g_Rp[MAXNODES * EMB];
__device__ __align__(128) float g_acc[MAXNODES * EMB];
__device__ __align__(128) float g_deg[MAXNODES];
__device__ __align__(128) float g_Wc[EMB * EMB];     // sp * (W1a @ Wf)
__device__ __align__(128) float g_bvec[EMB];         // sp * (W1a @ bf)
// fragment-packed hi-only tf32 weights: [m][(ks*16+nt)*32+lane] = {b0h,b1h}
// m: 0=W_left 1=W_right 2=Wc 3=W1b 4=W_out2
__device__ __align__(128) float2 g_frag[5][8192];
__device__ int g_is64;

// ---------------- helpers ----------------
__device__ __forceinline__ uint32_t tf32r(float v) {
    uint32_t r;
    asm("cvt.rna.tf32.f32 %0, %1;" : "=r"(r) : "f"(v));
    return r;
}
__device__ __forceinline__ void mma8(float* c, uint32_t a0, uint32_t a1,
                                     uint32_t a2, uint32_t a3,
                                     uint32_t b0, uint32_t b1) {
    asm volatile(
        "mma.sync.aligned.m16n8k8.row.col.f32.tf32.tf32.f32 "
        "{%0,%1,%2,%3}, {%4,%5,%6,%7}, {%8,%9}, {%0,%1,%2,%3};"
        : "+f"(c[0]), "+f"(c[1]), "+f"(c[2]), "+f"(c[3])
        : "r"(a0), "r"(a1), "r"(a2), "r"(a3), "r"(b0), "r"(b1));
}
__device__ __forceinline__ void red_add_v4(float* p, float4 v) {
    asm volatile("red.global.add.v4.f32 [%0], {%1, %2, %3, %4};"
                 :: "l"(p), "f"(v.x), "f"(v.y), "f"(v.z), "f"(v.w) : "memory");
}
__device__ __forceinline__ void red_add_f32(float* p, float v) {
    asm volatile("red.global.add.f32 [%0], %1;" :: "l"(p), "f"(v) : "memory");
}

// ---------------------------------------------------------------------------
// 64x128x128 2-pass compensated-TF32 GEMM (D = Ah@Bh + Al@Bh), 8 warps.
// Warp (rg, ch): rows rg*16..+15, cols ch*64..+63 (8 n-tiles). acc[8][4].
// As: smem, raw f32, ASTRIDE-padded. Bf: hi-only fragments (global/L2).
// ---------------------------------------------------------------------------
__device__ __forceinline__ void gemm64(const float* __restrict__ As,
                                       const float2* __restrict__ Bf,
                                       float acc[8][4], int rg, int ch, int lane) {
    const int g = lane >> 2, t = lane & 3;
    const float* r0 = As + (rg * 16 + g) * ASTRIDE;
    const float* r8 = r0 + 8 * ASTRIDE;
#pragma unroll
    for (int ks = 0; ks < 16; ks++) {
        const int k = ks * 8 + t;
        const float a0 = r0[k], a1 = r8[k], a2 = r0[k + 4], a3 = r8[k + 4];
        const uint32_t a0h = tf32r(a0), a1h = tf32r(a1);
        const uint32_t a2h = tf32r(a2), a3h = tf32r(a3);
        const uint32_t a0l = tf32r(a0 - __uint_as_float(a0h));
        const uint32_t a1l = tf32r(a1 - __uint_as_float(a1h));
        const uint32_t a2l = tf32r(a2 - __uint_as_float(a2h));
        const uint32_t a3l = tf32r(a3 - __uint_as_float(a3h));
        const float2* bp = Bf + ks * 512 + ch * 256 + lane;
#pragma unroll
        for (int nt = 0; nt < 8; nt++) {
            const float2 b = bp[nt * 32];
            const uint32_t b0h = __float_as_uint(b.x), b1h = __float_as_uint(b.y);
            mma8(acc[nt], a0h, a1h, a2h, a3h, b0h, b1h);
            mma8(acc[nt], a0l, a1l, a2l, a3l, b0h, b1h);
        }
    }
}

// stage TROWS rows of a row-major [n, 128] matrix into padded smem (zero-fill OOB)
__device__ __forceinline__ void stage_rows(const float* __restrict__ gptr, int row0,
                                           int n, float* As, int tid) {
    for (int i = tid; i < TROWS * 32; i += 256) {
        const int r = i >> 5, c4 = i & 31;
        float4 v = make_float4(0.f, 0.f, 0.f, 0.f);
        if (row0 + r < n)
            v = ((const float4*)(gptr + (size_t)(row0 + r) * EMB))[c4];
        *(float4*)(As + r * ASTRIDE + c4 * 4) = v;
    }
}

// ---------------------------------------------------------------------------
// prep1: detect idx width; zero g_acc/g_deg; Wc = sp*(W1a@Wf); bvec = sp*(W1a@bf).
// ---------------------------------------------------------------------------
__global__ void prep1_kernel(const float* __restrict__ Wf, const float* __restrict__ W1,
                             const float* __restrict__ bf, const float* __restrict__ sp_p,
                             const long long* __restrict__ eidx, int n_edges,
                             int n4, int n_right) {
    const int idx = blockIdx.x * blockDim.x + threadIdx.x;
    if (idx == 0) {
        int m = n_edges < 64 ? n_edges : 64;
        int ok = 1;
        for (int i = 0; i < m; i++) {
            long long v = eidx[i];
            if (v < 0 || v >= (1LL << 31)) { ok = 0; break; }
        }
        g_is64 = ok;
    }
    if (idx < n4) ((float4*)g_acc)[idx] = make_float4(0.f, 0.f, 0.f, 0.f);
    if (idx < n_right) g_deg[idx] = 0.f;
    if (idx < EMB * EMB) {
        const int j = idx >> 7, k = idx & 127;
        float s = 0.f;
        for (int m = 0; m < EMB; m++)
            s = fmaf(W1[j * 2 * EMB + m], Wf[m * EMB + k], s);
        g_Wc[idx] = s * sp_p[0];
    }
    if (idx < EMB) {
        float s = 0.f;
        for (int m = 0; m < EMB; m++)
            s = fmaf(W1[idx * 2 * EMB + m], bf[m], s);
        g_bvec[idx] = s * sp_p[0];
    }
}

// ---------------------------------------------------------------------------
// prep2: pack fragment-ordered hi tf32 weights.
// frag[(ks*16+nt)*32+lane] = {hi(W[n][k0]), hi(W[n][k1])}
//   n = nt*8 + lane/4, k0 = ks*8 + lane%4, k1 = k0+4
// ---------------------------------------------------------------------------
__global__ void prep2_kernel(const float* __restrict__ Wl, const float* __restrict__ Wr,
                             const float* __restrict__ W1, const float* __restrict__ W2) {
    const int idx = blockIdx.x * blockDim.x + threadIdx.x;
    if (idx >= 5 * 8192) return;
    const int m = idx >> 13, r = idx & 8191;
    const int lane = r & 31, nt = (r >> 5) & 15, ks = r >> 9;   // ks in [0,16)
    const int g = lane >> 2, t = lane & 3;
    const int n = nt * 8 + g, k0 = ks * 8 + t;

    const float* src; int L, off;
    switch (m) {
        case 0:  src = Wl;   L = EMB;     off = 0;   break;
        case 1:  src = Wr;   L = EMB;     off = 0;   break;
        case 2:  src = g_Wc; L = EMB;     off = 0;   break;
        case 3:  src = W1;   L = 2 * EMB; off = EMB; break;
        default: src = W2;   L = EMB;     off = 0;   break;
    }
    const float v0 = src[n * L + off + k0];
    const float v1 = src[n * L + off + k0 + 4];
    g_frag[m][r] = make_float2(__uint_as_float(tf32r(v0)),
                               __uint_as_float(tf32r(v1)));
}

// ---------------------------------------------------------------------------
// Tensor-core projections: Lp = left@WL^T + bL ; Rp = right@WR^T
// 256 threads / 8 warps; block tile = 64 rows, warp tile = 16 x 64.
// ---------------------------------------------------------------------------
__global__ __launch_bounds__(256) void proj_mma(
    const float* __restrict__ left, const float* __restrict__ right,
    const float* __restrict__ bL, int n_left, int n_right, int blocksL)
{
    extern __shared__ float sm[];
    float* As = sm;
    float* sBias = sm + TROWS * ASTRIDE;
    const int tid = threadIdx.x, warp = tid >> 5, lane = tid & 31;
    const int rg = warp >> 1, ch = warp & 1;

    const float* A; const float2* Bf; float* outp; int n, row0;
    if ((int)blockIdx.x < blocksL) {
        A = left;  Bf = g_frag[0]; outp = g_Lp; n = n_left;
        row0 = blockIdx.x * TROWS;
        if (tid < 128) sBias[tid] = bL[tid];
    } else {
        A = right; Bf = g_frag[1]; outp = g_Rp; n = n_right;
        row0 = (blockIdx.x - blocksL) * TROWS;
        if (tid < 128) sBias[tid] = 0.f;
    }
    stage_rows(A, row0, n, As, tid);
    __syncthreads();

    float acc[8][4];
#pragma unroll
    for (int nt = 0; nt < 8; nt++)
#pragma unroll
        for (int i = 0; i < 4; i++) acc[nt][i] = 0.f;

    gemm64(As, Bf, acc, rg, ch, lane);

    const int g = lane >> 2, t = lane & 3;
    const int r0 = row0 + rg * 16 + g, r1 = r0 + 8;
#pragma unroll
    for (int nt = 0; nt < 8; nt++) {
        const int c = (ch * 8 + nt) * 8 + 2 * t;
        if (r0 < n) {
            float2 o = make_float2(acc[nt][0] + sBias[c], acc[nt][1] + sBias[c + 1]);
            *(float2*)(outp + (size_t)r0 * EMB + c) = o;
        }
        if (r1 < n) {
            float2 o = make_float2(acc[nt][2] + sBias[c], acc[nt][3] + sBias[c + 1]);
            *(float2*)(outp + (size_t)r1 * EMB + c) = o;
        }
    }
}

// ---------------------------------------------------------------------------
// Edge stage (GEMM commuted out): t = relu((Lp[s]+Rp[d]+ef*we)*scale);
// red.v4 into g_acc[d]; count degree. One warp per edge.
// ---------------------------------------------------------------------------
__global__ __launch_bounds__(256) void edge_kernel(
    const void* __restrict__ eidx_raw, const float* __restrict__ ef,
    const float* __restrict__ wedge, const float* __restrict__ scale_p,
    int n_edges)
{
    const int warp = threadIdx.x >> 5, lane = threadIdx.x & 31;
    const int ge = blockIdx.x * 8 + warp;
    if (ge >= n_edges) return;

    int s, d;
    if (g_is64) {
        const long long* __restrict__ e64 = (const long long*)eidx_raw;
        s = (int)e64[ge]; d = (int)e64[n_edges + ge];
    } else {
        const int* __restrict__ e32 = (const int*)eidx_raw;
        s = e32[ge]; d = e32[n_edges + ge];
    }
    const float fe = ef[ge];
    const float scale = scale_p[0];

    const float4 we = ((const float4*)wedge)[lane];
    const float4 l = ((const float4*)(g_Lp + (size_t)s * EMB))[lane];
    const float4 r = ((const float4*)(g_Rp + (size_t)d * EMB))[lane];

    float4 t;
    t.x = fmaxf(fmaf(fe, we.x, l.x + r.x) * scale, 0.f);
    t.y = fmaxf(fmaf(fe, we.y, l.y + r.y) * scale, 0.f);
    t.z = fmaxf(fmaf(fe, we.z, l.z + r.z) * scale, 0.f);
    t.w = fmaxf(fmaf(fe, we.w, l.w + r.w) * scale, 0.f);

    red_add_v4(&g_acc[(size_t)d * EMB + lane * 4], t);
    if (lane == 0) red_add_f32(&g_deg[d], 1.0f);
}

// ---------------------------------------------------------------------------
// Fused output: u = relu(acc@Wc^T + deg*bvec + right@W1b^T + b1);
//               out = u@W2^T + b2.   (Wf folded into Wc at prep.)
// 256 threads / 8 warps; 64-row tile; ONE shared A buffer reused across
// the three GEMM phases (acc tile -> right tile -> u tile).
// ---------------------------------------------------------------------------
__global__ __launch_bounds__(256) void out_mma(
    const float* __restrict__ right, const float* __restrict__ b1,
    const float* __restrict__ b2, float* __restrict__ out, int n_right)
{
    extern __shared__ float sm[];
    float* As = sm;
    float* sBv = sm + TROWS * ASTRIDE;
    float* sB1 = sBv + 128;
    float* sB2 = sB1 + 128;
    const int tid = threadIdx.x, warp = tid >> 5, lane = tid & 31;
    const int rg = warp >> 1, ch = warp & 1;
    const int row0 = blockIdx.x * TROWS;

    if (tid < 128) {
        sBv[tid] = g_bvec[tid];
        sB1[tid] = b1[tid];
        sB2[tid] = b2[tid];
    }

    float acc[8][4];
#pragma unroll
    for (int nt = 0; nt < 8; nt++)
#pragma unroll
        for (int i = 0; i < 4; i++) acc[nt][i] = 0.f;

    // Phase 1: acc_tile @ Wc^T
    stage_rows(g_acc, row0, n_right, As, tid);
    __syncthreads();
    gemm64(As, g_frag[2], acc, rg, ch, lane);
    __syncthreads();   // everyone done reading As

    // Phase 2: + right @ W1b^T
    stage_rows(right, row0, n_right, As, tid);
    __syncthreads();
    gemm64(As, g_frag[3], acc, rg, ch, lane);

    const int g = lane >> 2, t = lane & 3;
    const int sr0 = rg * 16 + g, sr1 = sr0 + 8;
    const float d0 = (row0 + sr0 < n_right) ? g_deg[row0 + sr0] : 0.f;
    const float d1 = (row0 + sr1 < n_right) ? g_deg[row0 + sr1] : 0.f;
    __syncthreads();   // everyone done reading As

    // u = relu(acc + deg*bvec + b1) -> As
#pragma unroll
    for (int nt = 0; nt < 8; nt++) {
        const int c = (ch * 8 + nt) * 8 + 2 * t;
        As[sr0 * ASTRIDE + c]     = fmaxf(acc[nt][0] + d0 * sBv[c]     + sB1[c],     0.f);
        As[sr0 * ASTRIDE + c + 1] = fmaxf(acc[nt][1] + d0 * sBv[c + 1] + sB1[c + 1], 0.f);
        As[sr1 * ASTRIDE + c]     = fmaxf(acc[nt][2] + d1 * sBv[c]     + sB1[c],     0.f);
        As[sr1 * ASTRIDE + c + 1] = fmaxf(acc[nt][3] + d1 * sBv[c + 1] + sB1[c + 1], 0.f);
    }
    __syncthreads();

    // Phase 3: u @ W2^T
#pragma unroll
    for (int nt = 0; nt < 8; nt++)
#pragma unroll
        for (int i = 0; i < 4; i++) acc[nt][i] = 0.f;

    gemm64(As, g_frag[4], acc, rg, ch, lane);

    const int r0g = row0 + sr0, r1g = row0 + sr1;
#pragma unroll
    for (int nt = 0; nt < 8; nt++) {
        const int c = (ch * 8 + nt) * 8 + 2 * t;
        if (r0g < n_right) {
            float2 o = make_float2(acc[nt][0] + sB2[c], acc[nt][1] + sB2[c + 1]);
            *(float2*)(out + (size_t)r0g * EMB + c) = o;
        }
        if (r1g < n_right) {
            float2 o = make_float2(acc[nt][2] + sB2[c], acc[nt][3] + sB2[c + 1]);
            *(float2*)(out + (size_t)r1g * EMB + c) = o;
        }
    }
}

// ---------------------------------------------------------------------------
extern "C" void kernel_launch(void* const* d_in, const int* in_sizes, int n_in,
                              void* d_out, int out_size)
{
    const float* left   = (const float*)d_in[0];
    const void*  eidx   = d_in[1];
    const float* ef     = (const float*)d_in[2];
    const float* right  = (const float*)d_in[3];
    // d_in[4] = scatter_out_size scalar (derived from right_features instead)
    const float* W_left      = (const float*)d_in[5];
    const float* b_left      = (const float*)d_in[6];
    const float* W_edge      = (const float*)d_in[7];
    const float* W_right     = (const float*)d_in[8];
    const float* scale_final = (const float*)d_in[9];
    const float* W_final     = (const float*)d_in[10];
    const float* b_final     = (const float*)d_in[11];
    const float* scale_post  = (const float*)d_in[12];
    const float* W_out1      = (const float*)d_in[13];
    const float* b_out1      = (const float*)d_in[14];
    const float* W_out2      = (const float*)d_in[15];
    const float* b_out2      = (const float*)d_in[16];

    const int n_left  = in_sizes[0] / EMB;
    const int n_edges = in_sizes[2];          // edge_features count (EDGE_FEAT=1)
    const int n_right = in_sizes[3] / EMB;

    const int SM_PROJ = (TROWS * ASTRIDE + 128) * (int)sizeof(float);
    const int SM_OUT  = (TROWS * ASTRIDE + 3 * 128) * (int)sizeof(float);
    cudaFuncSetAttribute(proj_mma, cudaFuncAttributeMaxDynamicSharedMemorySize, SM_PROJ);
    cudaFuncSetAttribute(out_mma,  cudaFuncAttributeMaxDynamicSharedMemorySize, SM_OUT);

    // launch 0: detect idx width + zero accumulators + folded weight Wc/bvec
    const int n4 = n_right * EMB / 4;
    prep1_kernel<<<(n4 + 255) / 256, 256>>>(W_final, W_out1, b_final, scale_post,
                                            (const long long*)eidx, n_edges,
                                            n4, n_right);

    // launch 1: fragment-pack all weights (hi tf32)
    prep2_kernel<<<(5 * 8192 + 255) / 256, 256>>>(W_left, W_right, W_out1, W_out2);

    // launch 2: tensor-core projections
    const int blocksL = (n_left + TROWS - 1) / TROWS;
    const int blocksR = (n_right + TROWS - 1) / TROWS;
    proj_mma<<<blocksL + blocksR, 256, SM_PROJ>>>(left, right, b_left,
                                                  n_left, n_right, blocksL);

    // launch 3: edge gather-combine-relu-scatter
    edge_kernel<<<(n_edges + 7) / 8, 256>>>(eidx, ef, W_edge, scale_final, n_edges);

    // launch 4: fused output MLP (Wf folded into Wc)
    out_mma<<<(n_right + TROWS - 1) / TROWS, 256, SM_OUT>>>(right, b_out1, b_out2,
                                                            (float*)d_out, n_right);
}